// round 1
// baseline (speedup 1.0000x reference)
#include <cuda_runtime.h>
#include <math.h>

#define D_MODEL 1024
#define N_HEAD  16
#define D_K     64
#define T_SEQ   2048
#define BATCH   2

// Scratch (allocation-free rule: __device__ globals)
__device__ float g_qkv[(size_t)BATCH * T_SEQ * 3 * D_MODEL];   // [B,T,3,H,Dk] flat
__device__ float g_attn[(size_t)BATCH * T_SEQ * D_MODEL];      // [B,T,H,Dk] flat

// ---------------------------------------------------------------------------
// GEMM: C[M,N] = A[M,K] @ B[N,K]^T + bias[N]   (both A and B K-major)
// BM=128, BN=128, BK=8, 256 threads, 8x8 per-thread tile.
// ---------------------------------------------------------------------------
__global__ __launch_bounds__(256) void gemm_nt_bias(
    const float* __restrict__ A, const float* __restrict__ B,
    const float* __restrict__ bias, float* __restrict__ C,
    int M, int N, int K)
{
    const int BM = 128, BN = 128, BK = 8;
    __shared__ float As[BK][BM];
    __shared__ float Bs[BK][BN];

    const int t  = threadIdx.x;
    const int tx = t & 15;          // 0..15 -> n
    const int ty = t >> 4;          // 0..15 -> m
    const int m0 = blockIdx.y * BM;
    const int n0 = blockIdx.x * BN;

    const int lr = t >> 1;          // 0..127 row within tile
    const int lc = (t & 1) * 4;     // 0 or 4 (k offset)

    float acc[8][8];
#pragma unroll
    for (int i = 0; i < 8; i++)
#pragma unroll
        for (int j = 0; j < 8; j++) acc[i][j] = 0.f;

    for (int k0 = 0; k0 < K; k0 += BK) {
        float4 av = *(const float4*)&A[(size_t)(m0 + lr) * K + k0 + lc];
        float4 bv = *(const float4*)&B[(size_t)(n0 + lr) * K + k0 + lc];
        As[lc + 0][lr] = av.x; As[lc + 1][lr] = av.y;
        As[lc + 2][lr] = av.z; As[lc + 3][lr] = av.w;
        Bs[lc + 0][lr] = bv.x; Bs[lc + 1][lr] = bv.y;
        Bs[lc + 2][lr] = bv.z; Bs[lc + 3][lr] = bv.w;
        __syncthreads();

#pragma unroll
        for (int k = 0; k < BK; k++) {
            float a[8], b[8];
            *(float4*)&a[0] = *(const float4*)&As[k][ty * 8];
            *(float4*)&a[4] = *(const float4*)&As[k][ty * 8 + 4];
            *(float4*)&b[0] = *(const float4*)&Bs[k][tx * 8];
            *(float4*)&b[4] = *(const float4*)&Bs[k][tx * 8 + 4];
#pragma unroll
            for (int i = 0; i < 8; i++)
#pragma unroll
                for (int j = 0; j < 8; j++)
                    acc[i][j] += a[i] * b[j];
        }
        __syncthreads();
    }

#pragma unroll
    for (int i = 0; i < 8; i++) {
        int m = m0 + ty * 8 + i;
#pragma unroll
        for (int j = 0; j < 8; j++) {
            int n = n0 + tx * 8 + j;
            C[(size_t)m * N + n] = acc[i][j] + bias[n];
        }
    }
}

// ---------------------------------------------------------------------------
// Flash attention (fp32, online softmax).
// Block: 256 threads handles (b, h, 64-query tile). S tiles of 64.
// Thread layout: q = t>>2 (0..63), g = t&3. In score phase thread owns
// s in [g*16, g*16+16); in PV phase thread owns d in [g*16, g*16+16).
// ---------------------------------------------------------------------------
#define PAD 68   // row stride in floats (keeps float4 alignment, skews banks)

__global__ __launch_bounds__(256) void attn_kernel()
{
    extern __shared__ float smem[];
    float (*Qs)[PAD] = (float (*)[PAD])(smem);
    float (*Ks)[PAD] = (float (*)[PAD])(smem + 64 * PAD);
    float (*Vs)[PAD] = (float (*)[PAD])(smem + 2 * 64 * PAD);
    float (*Ps)[PAD] = (float (*)[PAD])(smem + 3 * 64 * PAD);

    const int t  = threadIdx.x;
    const int b  = blockIdx.z;
    const int h  = blockIdx.y;
    const int q0 = blockIdx.x * 64;
    const int q  = t >> 2;
    const int g  = t & 3;
    const float scale = 0.125f;  // 1/sqrt(64)

    // Load Q tile (scaled)
    for (int idx = t; idx < 64 * 16; idx += 256) {
        int r = idx >> 4, c4 = (idx & 15) * 4;
        const float4 v = *(const float4*)
            &g_qkv[(((size_t)(b * T_SEQ + q0 + r)) * 3 + 0) * D_MODEL + h * 64 + c4];
        Qs[r][c4 + 0] = v.x * scale; Qs[r][c4 + 1] = v.y * scale;
        Qs[r][c4 + 2] = v.z * scale; Qs[r][c4 + 3] = v.w * scale;
    }

    float m = -1e30f, l = 0.f;
    float acc[16];
#pragma unroll
    for (int i = 0; i < 16; i++) acc[i] = 0.f;

    for (int s0 = 0; s0 < T_SEQ; s0 += 64) {
        __syncthreads();  // protect Ks/Vs/Ps from previous iteration readers
        // Load K and V tiles
        for (int idx = t; idx < 64 * 16; idx += 256) {
            int r = idx >> 4, c4 = (idx & 15) * 4;
            size_t base = ((size_t)(b * T_SEQ + s0 + r)) * 3 * D_MODEL + h * 64 + c4;
            float4 kv = *(const float4*)&g_qkv[base + D_MODEL];
            float4 vv = *(const float4*)&g_qkv[base + 2 * D_MODEL];
            Ks[r][c4 + 0] = kv.x; Ks[r][c4 + 1] = kv.y;
            Ks[r][c4 + 2] = kv.z; Ks[r][c4 + 3] = kv.w;
            Vs[r][c4 + 0] = vv.x; Vs[r][c4 + 1] = vv.y;
            Vs[r][c4 + 2] = vv.z; Vs[r][c4 + 3] = vv.w;
        }
        __syncthreads();

        // Scores for my 16 s values
        float sc[16];
#pragma unroll
        for (int j = 0; j < 16; j++) sc[j] = 0.f;
#pragma unroll 4
        for (int d0 = 0; d0 < 64; d0 += 4) {
            float4 qv = *(const float4*)&Qs[q][d0];
#pragma unroll
            for (int j = 0; j < 16; j++) {
                float4 kv = *(const float4*)&Ks[g * 16 + j][d0];
                sc[j] += qv.x * kv.x + qv.y * kv.y + qv.z * kv.z + qv.w * kv.w;
            }
        }

        // Online softmax: quad (lanes q*4+g, g=0..3) shares row q
        float mx = sc[0];
#pragma unroll
        for (int j = 1; j < 16; j++) mx = fmaxf(mx, sc[j]);
        mx = fmaxf(mx, __shfl_xor_sync(0xffffffffu, mx, 1));
        mx = fmaxf(mx, __shfl_xor_sync(0xffffffffu, mx, 2));
        float m_new = fmaxf(m, mx);
        float corr = __expf(m - m_new);
        float ls = 0.f;
#pragma unroll
        for (int j = 0; j < 16; j++) {
            float p = __expf(sc[j] - m_new);
            Ps[q][g * 16 + j] = p;
            ls += p;
        }
        ls += __shfl_xor_sync(0xffffffffu, ls, 1);
        ls += __shfl_xor_sync(0xffffffffu, ls, 2);
        l = l * corr + ls;
        m = m_new;
#pragma unroll
        for (int i = 0; i < 16; i++) acc[i] *= corr;

        __syncwarp();  // Ps row q written entirely by this warp's quad

        // PV: accumulate over all 64 s into my 16 d
        for (int s = 0; s < 64; s++) {
            float p = Ps[q][s];
#pragma unroll
            for (int i0 = 0; i0 < 16; i0 += 4) {
                float4 vv = *(const float4*)&Vs[s][g * 16 + i0];
                acc[i0 + 0] += p * vv.x; acc[i0 + 1] += p * vv.y;
                acc[i0 + 2] += p * vv.z; acc[i0 + 3] += p * vv.w;
            }
        }
    }

    float inv_l = 1.f / l;
    size_t obase = ((size_t)(b * T_SEQ + q0 + q)) * D_MODEL + h * 64 + g * 16;
#pragma unroll
    for (int i0 = 0; i0 < 16; i0 += 4) {
        float4 o;
        o.x = acc[i0 + 0] * inv_l; o.y = acc[i0 + 1] * inv_l;
        o.z = acc[i0 + 2] * inv_l; o.w = acc[i0 + 3] * inv_l;
        *(float4*)&g_attn[obase + i0] = o;
    }
}

// ---------------------------------------------------------------------------
extern "C" void kernel_launch(void* const* d_in, const int* in_sizes, int n_in,
                              void* d_out, int out_size)
{
    const float* x      = (const float*)d_in[0];
    const float* qkv_w  = (const float*)d_in[1];
    const float* qkv_b  = (const float*)d_in[2];
    const float* out_w  = (const float*)d_in[3];
    const float* out_b  = (const float*)d_in[4];
    float* out = (float*)d_out;

    float *qkv_buf, *attn_buf;
    cudaGetSymbolAddress((void**)&qkv_buf, g_qkv);
    cudaGetSymbolAddress((void**)&attn_buf, g_attn);

    const int M = BATCH * T_SEQ;            // 4096
    const int smem_attn = 4 * 64 * PAD * sizeof(float);  // 69632 B
    cudaFuncSetAttribute(attn_kernel,
                         cudaFuncAttributeMaxDynamicSharedMemorySize, smem_attn);

    // 1) QKV projection: [4096,1024] @ [3072,1024]^T + b -> [4096,3072]
    {
        dim3 grid(3 * D_MODEL / 128, M / 128);
        gemm_nt_bias<<<grid, 256>>>(x, qkv_w, qkv_b, qkv_buf,
                                    M, 3 * D_MODEL, D_MODEL);
    }
    // 2) Attention
    {
        dim3 grid(T_SEQ / 64, N_HEAD, BATCH);
        attn_kernel<<<grid, 256, smem_attn>>>();
    }
    // 3) Output projection: [4096,1024] @ [1024,1024]^T + b -> d_out
    {
        dim3 grid(D_MODEL / 128, M / 128);
        gemm_nt_bias<<<grid, 256>>>(attn_buf, out_w, out_b, out,
                                    M, D_MODEL, D_MODEL);
    }
}

// round 2
// speedup vs baseline: 3.2513x; 3.2513x over previous
#include <cuda_runtime.h>
#include <math.h>

#define D_MODEL 1024
#define N_HEAD  16
#define D_K     64
#define T_SEQ   2048
#define BATCH   2

// Scratch (allocation-free rule: __device__ globals)
__device__ float g_qkv[(size_t)BATCH * T_SEQ * 3 * D_MODEL];   // [B,T,3,H,Dk] flat
__device__ float g_attn[(size_t)BATCH * T_SEQ * D_MODEL];      // [B,T,H,Dk] flat

// ---------------------------------------------------------------------------
// GEMM: C[M,N] = A[M,K] @ B[N,K]^T + bias[N]   (both A and B K-major)
// BM=128, BN=128, BK=8, 256 threads, 8x8 per-thread tile.  (near scalar-fp32 peak)
// ---------------------------------------------------------------------------
__global__ __launch_bounds__(256) void gemm_nt_bias(
    const float* __restrict__ A, const float* __restrict__ B,
    const float* __restrict__ bias, float* __restrict__ C,
    int M, int N, int K)
{
    const int BM = 128, BN = 128, BK = 8;
    __shared__ float As[BK][BM];
    __shared__ float Bs[BK][BN];

    const int t  = threadIdx.x;
    const int tx = t & 15;
    const int ty = t >> 4;
    const int m0 = blockIdx.y * BM;
    const int n0 = blockIdx.x * BN;

    const int lr = t >> 1;
    const int lc = (t & 1) * 4;

    float acc[8][8];
#pragma unroll
    for (int i = 0; i < 8; i++)
#pragma unroll
        for (int j = 0; j < 8; j++) acc[i][j] = 0.f;

    for (int k0 = 0; k0 < K; k0 += BK) {
        float4 av = *(const float4*)&A[(size_t)(m0 + lr) * K + k0 + lc];
        float4 bv = *(const float4*)&B[(size_t)(n0 + lr) * K + k0 + lc];
        As[lc + 0][lr] = av.x; As[lc + 1][lr] = av.y;
        As[lc + 2][lr] = av.z; As[lc + 3][lr] = av.w;
        Bs[lc + 0][lr] = bv.x; Bs[lc + 1][lr] = bv.y;
        Bs[lc + 2][lr] = bv.z; Bs[lc + 3][lr] = bv.w;
        __syncthreads();

#pragma unroll
        for (int k = 0; k < BK; k++) {
            float a[8], b[8];
            *(float4*)&a[0] = *(const float4*)&As[k][ty * 8];
            *(float4*)&a[4] = *(const float4*)&As[k][ty * 8 + 4];
            *(float4*)&b[0] = *(const float4*)&Bs[k][tx * 8];
            *(float4*)&b[4] = *(const float4*)&Bs[k][tx * 8 + 4];
#pragma unroll
            for (int i = 0; i < 8; i++)
#pragma unroll
                for (int j = 0; j < 8; j++)
                    acc[i][j] += a[i] * b[j];
        }
        __syncthreads();
    }

#pragma unroll
    for (int i = 0; i < 8; i++) {
        int m = m0 + ty * 8 + i;
#pragma unroll
        for (int j = 0; j < 8; j++) {
            int n = n0 + tx * 8 + j;
            C[(size_t)m * N + n] = acc[i][j] + bias[n];
        }
    }
}

// ---------------------------------------------------------------------------
// Flash attention, register-tiled (fp32, online softmax).
// Block = 256 threads = (tx 0..15, ty 0..15), handles 128 queries of one (b,h).
// S tile = 128. Score GEMM: 8x8 per thread (q=ty*8.., s=tx*8..).
// PV GEMM: 8x4 per thread (q=ty*8.., d=tx*4..).
// Smem: Qs/Ks d-major [64][132], Vs s-major [128][68], Ps s-major [128][132].
// K/V for next tile prefetched into registers during PV phase.
// ---------------------------------------------------------------------------
#define TQ 128
#define TS 128
#define QK_STR 132
#define V_STR  68
#define P_STR  132
#define SMEM_FLOATS (2*64*QK_STR + 128*V_STR + 128*P_STR)

__global__ __launch_bounds__(256, 1) void attn_kernel()
{
    extern __shared__ float sm[];
    float* Qs = sm;                       // [64][QK_STR]
    float* Ks = sm + 64 * QK_STR;         // [64][QK_STR]
    float* Vs = Ks + 64 * QK_STR;         // [128][V_STR]
    float* Ps = Vs + 128 * V_STR;         // [128][P_STR]

    const int t  = threadIdx.x;
    const int tx = t & 15;
    const int ty = t >> 4;
    const int b  = blockIdx.z;
    const int h  = blockIdx.y;
    const int q0 = blockIdx.x * TQ;
    const int rowstr = 3 * D_MODEL;
    const float scale = 0.125f;           // 1/sqrt(64)

    // ---- load Q tile, transposed to d-major, pre-scaled ----
#pragma unroll
    for (int i = 0; i < 8; i++) {
        int slot = i * 256 + t;
        int r  = slot >> 4;
        int c4 = (slot & 15) << 2;
        float4 v = *(const float4*)
            &g_qkv[(size_t)(b * T_SEQ + q0 + r) * rowstr + h * 64 + c4];
        Qs[(c4 + 0) * QK_STR + r] = v.x * scale;
        Qs[(c4 + 1) * QK_STR + r] = v.y * scale;
        Qs[(c4 + 2) * QK_STR + r] = v.z * scale;
        Qs[(c4 + 3) * QK_STR + r] = v.w * scale;
    }

    float m_i[8], l_i[8];
    float4 acc_o[8];
#pragma unroll
    for (int i = 0; i < 8; i++) {
        m_i[i] = -1e30f; l_i[i] = 0.f;
        acc_o[i] = make_float4(0.f, 0.f, 0.f, 0.f);
    }

    // ---- prefetch K/V tile 0 into registers ----
    float4 kr[8], vr[8];
#pragma unroll
    for (int i = 0; i < 8; i++) {
        int slot = i * 256 + t;
        int r  = slot >> 4;
        int c4 = (slot & 15) << 2;
        size_t base = (size_t)(b * T_SEQ + r) * rowstr + h * 64 + c4;
        kr[i] = *(const float4*)&g_qkv[base + D_MODEL];
        vr[i] = *(const float4*)&g_qkv[base + 2 * D_MODEL];
    }

    for (int s0 = 0; s0 < T_SEQ; s0 += TS) {
        __syncthreads();   // previous tile's readers of Ks/Vs are done

        // ---- store prefetched K (transposed) and V (s-major) ----
#pragma unroll
        for (int i = 0; i < 8; i++) {
            int slot = i * 256 + t;
            int r  = slot >> 4;
            int c4 = (slot & 15) << 2;
            Ks[(c4 + 0) * QK_STR + r] = kr[i].x;
            Ks[(c4 + 1) * QK_STR + r] = kr[i].y;
            Ks[(c4 + 2) * QK_STR + r] = kr[i].z;
            Ks[(c4 + 3) * QK_STR + r] = kr[i].w;
            *(float4*)&Vs[r * V_STR + c4] = vr[i];
        }
        __syncthreads();

        // ---- scores: acc[j=s][i=q] ----
        float acc[8][8];
#pragma unroll
        for (int j = 0; j < 8; j++)
#pragma unroll
            for (int i = 0; i < 8; i++) acc[j][i] = 0.f;

#pragma unroll 4
        for (int d = 0; d < 64; d++) {
            const float* qr = Qs + d * QK_STR + (ty << 3);
            const float* kq = Ks + d * QK_STR + (tx << 3);
            float4 a0 = *(const float4*)qr;
            float4 a1 = *(const float4*)(qr + 4);
            float4 b0 = *(const float4*)kq;
            float4 b1 = *(const float4*)(kq + 4);
            float av[8] = {a0.x, a0.y, a0.z, a0.w, a1.x, a1.y, a1.z, a1.w};
            float bv[8] = {b0.x, b0.y, b0.z, b0.w, b1.x, b1.y, b1.z, b1.w};
#pragma unroll
            for (int j = 0; j < 8; j++)
#pragma unroll
                for (int i = 0; i < 8; i++)
                    acc[j][i] += bv[j] * av[i];
        }

        // ---- online softmax (per q row; row spread over 16 tx lanes) ----
#pragma unroll
        for (int i = 0; i < 8; i++) {
            float mx = acc[0][i];
#pragma unroll
            for (int j = 1; j < 8; j++) mx = fmaxf(mx, acc[j][i]);
            mx = fmaxf(mx, __shfl_xor_sync(0xffffffffu, mx, 1));
            mx = fmaxf(mx, __shfl_xor_sync(0xffffffffu, mx, 2));
            mx = fmaxf(mx, __shfl_xor_sync(0xffffffffu, mx, 4));
            mx = fmaxf(mx, __shfl_xor_sync(0xffffffffu, mx, 8));
            float mn   = fmaxf(m_i[i], mx);
            float corr = __expf(m_i[i] - mn);
            m_i[i] = mn;
            float ls = 0.f;
#pragma unroll
            for (int j = 0; j < 8; j++) {
                float p = __expf(acc[j][i] - mn);
                acc[j][i] = p;
                ls += p;
            }
            ls += __shfl_xor_sync(0xffffffffu, ls, 1);
            ls += __shfl_xor_sync(0xffffffffu, ls, 2);
            ls += __shfl_xor_sync(0xffffffffu, ls, 4);
            ls += __shfl_xor_sync(0xffffffffu, ls, 8);
            l_i[i] = l_i[i] * corr + ls;
            acc_o[i].x *= corr; acc_o[i].y *= corr;
            acc_o[i].z *= corr; acc_o[i].w *= corr;
        }

        // ---- write P (s-major) as float4 fragments ----
#pragma unroll
        for (int j = 0; j < 8; j++) {
            float* pr = Ps + ((tx << 3) + j) * P_STR + (ty << 3);
            *(float4*)pr       = make_float4(acc[j][0], acc[j][1], acc[j][2], acc[j][3]);
            *(float4*)(pr + 4) = make_float4(acc[j][4], acc[j][5], acc[j][6], acc[j][7]);
        }

        // ---- prefetch next K/V tile (hidden under PV compute) ----
        if (s0 + TS < T_SEQ) {
#pragma unroll
            for (int i = 0; i < 8; i++) {
                int slot = i * 256 + t;
                int r  = slot >> 4;
                int c4 = (slot & 15) << 2;
                size_t base = (size_t)(b * T_SEQ + s0 + TS + r) * rowstr + h * 64 + c4;
                kr[i] = *(const float4*)&g_qkv[base + D_MODEL];
                vr[i] = *(const float4*)&g_qkv[base + 2 * D_MODEL];
            }
        }

        __syncthreads();   // Ps visible to all

        // ---- PV: acc_o[i=q][k=d] += P[q][s] * V[s][d] ----
#pragma unroll 2
        for (int s = 0; s < TS; s++) {
            const float* pr = Ps + s * P_STR + (ty << 3);
            float4 p0 = *(const float4*)pr;
            float4 p1 = *(const float4*)(pr + 4);
            float4 v  = *(const float4*)&Vs[s * V_STR + (tx << 2)];
            float pv[8] = {p0.x, p0.y, p0.z, p0.w, p1.x, p1.y, p1.z, p1.w};
#pragma unroll
            for (int i = 0; i < 8; i++) {
                acc_o[i].x += pv[i] * v.x;
                acc_o[i].y += pv[i] * v.y;
                acc_o[i].z += pv[i] * v.z;
                acc_o[i].w += pv[i] * v.w;
            }
        }
    }

    // ---- epilogue ----
#pragma unroll
    for (int i = 0; i < 8; i++) {
        float inv = 1.f / l_i[i];
        float4 o;
        o.x = acc_o[i].x * inv; o.y = acc_o[i].y * inv;
        o.z = acc_o[i].z * inv; o.w = acc_o[i].w * inv;
        size_t row = (size_t)(b * T_SEQ + q0 + (ty << 3) + i);
        *(float4*)&g_attn[row * D_MODEL + h * 64 + (tx << 2)] = o;
    }
}

// ---------------------------------------------------------------------------
extern "C" void kernel_launch(void* const* d_in, const int* in_sizes, int n_in,
                              void* d_out, int out_size)
{
    const float* x      = (const float*)d_in[0];
    const float* qkv_w  = (const float*)d_in[1];
    const float* qkv_b  = (const float*)d_in[2];
    const float* out_w  = (const float*)d_in[3];
    const float* out_b  = (const float*)d_in[4];
    float* out = (float*)d_out;

    float *qkv_buf, *attn_buf;
    cudaGetSymbolAddress((void**)&qkv_buf, g_qkv);
    cudaGetSymbolAddress((void**)&attn_buf, g_attn);

    const int M = BATCH * T_SEQ;            // 4096
    const int smem_attn = SMEM_FLOATS * sizeof(float);   // 169984 B
    static bool configured = false;
    if (!configured) {
        cudaFuncSetAttribute(attn_kernel,
                             cudaFuncAttributeMaxDynamicSharedMemorySize, smem_attn);
        configured = true;
    }

    // 1) QKV projection: [4096,1024] @ [3072,1024]^T + b -> [4096,3072]
    {
        dim3 grid(3 * D_MODEL / 128, M / 128);
        gemm_nt_bias<<<grid, 256>>>(x, qkv_w, qkv_b, qkv_buf,
                                    M, 3 * D_MODEL, D_MODEL);
    }
    // 2) Attention
    {
        dim3 grid(T_SEQ / TQ, N_HEAD, BATCH);
        attn_kernel<<<grid, 256, smem_attn>>>();
    }
    // 3) Output projection: [4096,1024] @ [1024,1024]^T + b -> d_out
    {
        dim3 grid(D_MODEL / 128, M / 128);
        gemm_nt_bias<<<grid, 256>>>(attn_buf, out_w, out_b, out,
                                    M, D_MODEL, D_MODEL);
    }
}

// round 4
// speedup vs baseline: 4.2577x; 1.3095x over previous
#include <cuda_runtime.h>
#include <cuda_bf16.h>
#include <math.h>

#define D_MODEL 1024
#define N_HEAD  16
#define T_SEQ   2048
#define BATCH   2
#define MTOT    4096
#define KDIM    1024
#define KSTEPS  64
#define NSTEPS  192

__device__ float         g_qkv[(size_t)MTOT * 3 * D_MODEL];
__device__ __nv_bfloat16 g_xh [(size_t)MTOT * D_MODEL];
__device__ __nv_bfloat16 g_xl [(size_t)MTOT * D_MODEL];
__device__ __nv_bfloat16 g_wqh[(size_t)3 * D_MODEL * D_MODEL];
__device__ __nv_bfloat16 g_wql[(size_t)3 * D_MODEL * D_MODEL];
__device__ __nv_bfloat16 g_woh[(size_t)D_MODEL * D_MODEL];
__device__ __nv_bfloat16 g_wol[(size_t)D_MODEL * D_MODEL];
__device__ __nv_bfloat16 g_ah [(size_t)MTOT * D_MODEL];
__device__ __nv_bfloat16 g_al [(size_t)MTOT * D_MODEL];

// fp32 -> bf16 hi/lo split
__global__ void split_kernel(const float* __restrict__ in,
                             __nv_bfloat16* __restrict__ hi,
                             __nv_bfloat16* __restrict__ lo, int n4)
{
    int i = blockIdx.x * blockDim.x + threadIdx.x;
    if (i >= n4) return;
    float4 v = ((const float4*)in)[i];
    float hx = __bfloat162float(__float2bfloat16(v.x));
    float hy = __bfloat162float(__float2bfloat16(v.y));
    float hz = __bfloat162float(__float2bfloat16(v.z));
    float hw = __bfloat162float(__float2bfloat16(v.w));
    __nv_bfloat162 hp0 = __floats2bfloat162_rn(hx, hy);
    __nv_bfloat162 hp1 = __floats2bfloat162_rn(hz, hw);
    __nv_bfloat162 lp0 = __floats2bfloat162_rn(v.x - hx, v.y - hy);
    __nv_bfloat162 lp1 = __floats2bfloat162_rn(v.z - hz, v.w - hw);
    ((__nv_bfloat162*)hi)[2 * i]     = hp0;
    ((__nv_bfloat162*)hi)[2 * i + 1] = hp1;
    ((__nv_bfloat162*)lo)[2 * i]     = lp0;
    ((__nv_bfloat162*)lo)[2 * i + 1] = lp1;
}

// ---------------------------------------------------------------------------
// Tensor-core GEMM (K fixed at 1024), 3-pass bf16 emulated fp32:
//   C = Ah@Bh^T + Ah@Bl^T + Al@Bh^T + bias
// Block 128x128, 8 warps (2m x 4n), warp tile 64x32, mma.sync m16n8k16.
// ---------------------------------------------------------------------------
#define GPITCH 24
#define GBUFB  (128 * GPITCH * 2)

__device__ __forceinline__ void cp16(unsigned int s, const void* g)
{
    asm volatile("cp.async.cg.shared.global [%0], [%1], 16;" :: "r"(s), "l"(g));
}
__device__ __forceinline__ void ldsm4(unsigned int* r, unsigned int a)
{
    asm volatile("ldmatrix.sync.aligned.m8n8.x4.shared.b16 {%0,%1,%2,%3}, [%4];"
                 : "=r"(r[0]), "=r"(r[1]), "=r"(r[2]), "=r"(r[3]) : "r"(a));
}
__device__ __forceinline__ void mma16816(float* c,
                                         const unsigned int* a,
                                         unsigned int e0, unsigned int e1)
{
    asm volatile(
        "mma.sync.aligned.m16n8k16.row.col.f32.bf16.bf16.f32 "
        "{%0,%1,%2,%3},{%4,%5,%6,%7},{%8,%9},{%0,%1,%2,%3};"
        : "+f"(c[0]), "+f"(c[1]), "+f"(c[2]), "+f"(c[3])
        : "r"(a[0]), "r"(a[1]), "r"(a[2]), "r"(a[3]), "r"(e0), "r"(e1));
}

__global__ __launch_bounds__(256, 2) void gemm_bf16x3(
    const __nv_bfloat16* __restrict__ Ah, const __nv_bfloat16* __restrict__ Al,
    const __nv_bfloat16* __restrict__ Bh, const __nv_bfloat16* __restrict__ Bl,
    const float* __restrict__ bias, float* __restrict__ C, int N)
{
    __shared__ __nv_bfloat16 sA[2][128 * GPITCH];
    __shared__ __nv_bfloat16 sB[2][128 * GPITCH];

    const int t    = threadIdx.x;
    const int lane = t & 31;
    const int warp = t >> 5;
    const int wm   = warp & 1;
    const int wn   = warp >> 1;
    const int m0   = blockIdx.y * 128;
    const int n0   = blockIdx.x * 128;

    const int ldrow   = t >> 1;
    const int ldoff   = (t & 1) * 8;

    const unsigned int sA0 = (unsigned int)__cvta_generic_to_shared(&sA[0][0]);
    const unsigned int sB0 = (unsigned int)__cvta_generic_to_shared(&sB[0][0]);
    const unsigned int a_st = sA0 + (unsigned int)(ldrow * GPITCH + ldoff) * 2u;
    const unsigned int b_st = sB0 + (unsigned int)(ldrow * GPITCH + ldoff) * 2u;
    const unsigned int a_ld = sA0 +
        (unsigned int)((wm * 64 + (lane & 15)) * GPITCH + (lane >> 4) * 8) * 2u;
    const unsigned int b_ld = sB0 +
        (unsigned int)((wn * 32 + (lane & 15)) * GPITCH + (lane >> 4) * 8) * 2u;

    float acc[4][4][4];
#pragma unroll
    for (int i = 0; i < 4; i++)
#pragma unroll
        for (int j = 0; j < 4; j++)
#pragma unroll
            for (int r = 0; r < 4; r++) acc[i][j][r] = 0.f;

    // prologue: stage step 0  (pass 0: Ah x Bh, k offset 0)
    {
        const __nv_bfloat16* ga = Ah + (size_t)(m0 + ldrow) * KDIM + ldoff;
        const __nv_bfloat16* gb = Bh + (size_t)(n0 + ldrow) * KDIM + ldoff;
        cp16(a_st, ga);
        cp16(b_st, gb);
        asm volatile("cp.async.commit_group;");
    }

    for (int s = 0; s < NSTEPS; s++) {
        const int cur = s & 1;
        if (s + 1 < NSTEPS) {
            const int sn = s + 1;
            const int p  = sn >> 6;            // pass index 0..2 (KSTEPS=64)
            const int kk = (sn & 63) << 4;     // k offset within pass
            const __nv_bfloat16* pa = (p == 2) ? Al : Ah;
            const __nv_bfloat16* pb = (p == 1) ? Bl : Bh;
            const __nv_bfloat16* ga = pa + (size_t)(m0 + ldrow) * KDIM + kk + ldoff;
            const __nv_bfloat16* gb = pb + (size_t)(n0 + ldrow) * KDIM + kk + ldoff;
            const unsigned int off = (unsigned int)((cur ^ 1) * GBUFB);
            cp16(a_st + off, ga);
            cp16(b_st + off, gb);
            asm volatile("cp.async.commit_group;");
            asm volatile("cp.async.wait_group 1;");
        } else {
            asm volatile("cp.async.wait_group 0;");
        }
        __syncthreads();

        const unsigned int coff = (unsigned int)(cur * GBUFB);
        unsigned int fa[4][4];
#pragma unroll
        for (int mf = 0; mf < 4; mf++)
            ldsm4(fa[mf], a_ld + coff + (unsigned int)(mf * 16 * GPITCH * 2));
        unsigned int fb[2][4];
#pragma unroll
        for (int pf = 0; pf < 2; pf++)
            ldsm4(fb[pf], b_ld + coff + (unsigned int)(pf * 16 * GPITCH * 2));

#pragma unroll
        for (int mf = 0; mf < 4; mf++) {
#pragma unroll
            for (int pf = 0; pf < 2; pf++) {
                mma16816(acc[mf][2 * pf + 0], fa[mf], fb[pf][0], fb[pf][2]);
                mma16816(acc[mf][2 * pf + 1], fa[mf], fb[pf][1], fb[pf][3]);
            }
        }
        __syncthreads();
    }

    const int gr = lane >> 2;
    const int gc = (lane & 3) * 2;
#pragma unroll
    for (int mf = 0; mf < 4; mf++) {
#pragma unroll
        for (int nf = 0; nf < 4; nf++) {
            int m = m0 + wm * 64 + mf * 16 + gr;
            int n = n0 + wn * 32 + nf * 8 + gc;
            float b0 = bias[n];
            float b1 = bias[n + 1];
            float2 v0;
            v0.x = acc[mf][nf][0] + b0;
            v0.y = acc[mf][nf][1] + b1;
            float2 v1;
            v1.x = acc[mf][nf][2] + b0;
            v1.y = acc[mf][nf][3] + b1;
            *(float2*)&C[(size_t)m * N + n]       = v0;
            *(float2*)&C[(size_t)(m + 8) * N + n] = v1;
        }
    }
}

// ---------------------------------------------------------------------------
// Flash attention, register-tiled fp32 (round-2 proven); epilogue writes the
// bf16 hi/lo split of the output directly.
// ---------------------------------------------------------------------------
#define TQ 128
#define TS 128
#define QK_STR 132
#define V_STR  68
#define P_STR  132
#define SMEM_FLOATS (2*64*QK_STR + 128*V_STR + 128*P_STR)

__global__ __launch_bounds__(256, 1) void attn_kernel()
{
    extern __shared__ float smf[];
    float* Qs = smf;
    float* Ks = smf + 64 * QK_STR;
    float* Vs = Ks + 64 * QK_STR;
    float* Ps = Vs + 128 * V_STR;

    const int t  = threadIdx.x;
    const int tx = t & 15;
    const int ty = t >> 4;
    const int b  = blockIdx.z;
    const int h  = blockIdx.y;
    const int q0 = blockIdx.x * TQ;
    const int rowstr = 3 * D_MODEL;
    const float scale = 0.125f;

#pragma unroll
    for (int i = 0; i < 8; i++) {
        int slot = i * 256 + t;
        int r  = slot >> 4;
        int c4 = (slot & 15) << 2;
        float4 v = *(const float4*)
            &g_qkv[(size_t)(b * T_SEQ + q0 + r) * rowstr + h * 64 + c4];
        Qs[(c4 + 0) * QK_STR + r] = v.x * scale;
        Qs[(c4 + 1) * QK_STR + r] = v.y * scale;
        Qs[(c4 + 2) * QK_STR + r] = v.z * scale;
        Qs[(c4 + 3) * QK_STR + r] = v.w * scale;
    }

    float m_i[8];
    float l_i[8];
    float4 acc_o[8];
#pragma unroll
    for (int i = 0; i < 8; i++) {
        m_i[i] = -1e30f;
        l_i[i] = 0.f;
        acc_o[i] = make_float4(0.f, 0.f, 0.f, 0.f);
    }

    float4 kr[8];
    float4 vr[8];
#pragma unroll
    for (int i = 0; i < 8; i++) {
        int slot = i * 256 + t;
        int r  = slot >> 4;
        int c4 = (slot & 15) << 2;
        size_t base = (size_t)(b * T_SEQ + r) * rowstr + h * 64 + c4;
        kr[i] = *(const float4*)&g_qkv[base + D_MODEL];
        vr[i] = *(const float4*)&g_qkv[base + 2 * D_MODEL];
    }

    for (int s0 = 0; s0 < T_SEQ; s0 += TS) {
        __syncthreads();
#pragma unroll
        for (int i = 0; i < 8; i++) {
            int slot = i * 256 + t;
            int r  = slot >> 4;
            int c4 = (slot & 15) << 2;
            Ks[(c4 + 0) * QK_STR + r] = kr[i].x;
            Ks[(c4 + 1) * QK_STR + r] = kr[i].y;
            Ks[(c4 + 2) * QK_STR + r] = kr[i].z;
            Ks[(c4 + 3) * QK_STR + r] = kr[i].w;
            *(float4*)&Vs[r * V_STR + c4] = vr[i];
        }
        __syncthreads();

        float sc[8][8];
#pragma unroll
        for (int j = 0; j < 8; j++)
#pragma unroll
            for (int i = 0; i < 8; i++) sc[j][i] = 0.f;

#pragma unroll 4
        for (int d = 0; d < 64; d++) {
            const float* qr = Qs + d * QK_STR + (ty << 3);
            const float* kq = Ks + d * QK_STR + (tx << 3);
            float4 qa = *(const float4*)qr;
            float4 qb = *(const float4*)(qr + 4);
            float4 ka = *(const float4*)kq;
            float4 kb = *(const float4*)(kq + 4);
            float av[8];
            av[0] = qa.x; av[1] = qa.y; av[2] = qa.z; av[3] = qa.w;
            av[4] = qb.x; av[5] = qb.y; av[6] = qb.z; av[7] = qb.w;
            float bv[8];
            bv[0] = ka.x; bv[1] = ka.y; bv[2] = ka.z; bv[3] = ka.w;
            bv[4] = kb.x; bv[5] = kb.y; bv[6] = kb.z; bv[7] = kb.w;
#pragma unroll
            for (int j = 0; j < 8; j++)
#pragma unroll
                for (int i = 0; i < 8; i++)
                    sc[j][i] += bv[j] * av[i];
        }

#pragma unroll
        for (int i = 0; i < 8; i++) {
            float mx = sc[0][i];
#pragma unroll
            for (int j = 1; j < 8; j++) mx = fmaxf(mx, sc[j][i]);
            mx = fmaxf(mx, __shfl_xor_sync(0xffffffffu, mx, 1));
            mx = fmaxf(mx, __shfl_xor_sync(0xffffffffu, mx, 2));
            mx = fmaxf(mx, __shfl_xor_sync(0xffffffffu, mx, 4));
            mx = fmaxf(mx, __shfl_xor_sync(0xffffffffu, mx, 8));
            float mn   = fmaxf(m_i[i], mx);
            float corr = __expf(m_i[i] - mn);
            m_i[i] = mn;
            float ls = 0.f;
#pragma unroll
            for (int j = 0; j < 8; j++) {
                float p = __expf(sc[j][i] - mn);
                sc[j][i] = p;
                ls += p;
            }
            ls += __shfl_xor_sync(0xffffffffu, ls, 1);
            ls += __shfl_xor_sync(0xffffffffu, ls, 2);
            ls += __shfl_xor_sync(0xffffffffu, ls, 4);
            ls += __shfl_xor_sync(0xffffffffu, ls, 8);
            l_i[i] = l_i[i] * corr + ls;
            acc_o[i].x *= corr;
            acc_o[i].y *= corr;
            acc_o[i].z *= corr;
            acc_o[i].w *= corr;
        }

#pragma unroll
        for (int j = 0; j < 8; j++) {
            float* pr = Ps + ((tx << 3) + j) * P_STR + (ty << 3);
            float4 w0;
            w0.x = sc[j][0]; w0.y = sc[j][1]; w0.z = sc[j][2]; w0.w = sc[j][3];
            float4 w1;
            w1.x = sc[j][4]; w1.y = sc[j][5]; w1.z = sc[j][6]; w1.w = sc[j][7];
            *(float4*)pr       = w0;
            *(float4*)(pr + 4) = w1;
        }

        if (s0 + TS < T_SEQ) {
#pragma unroll
            for (int i = 0; i < 8; i++) {
                int slot = i * 256 + t;
                int r  = slot >> 4;
                int c4 = (slot & 15) << 2;
                size_t base = (size_t)(b * T_SEQ + s0 + TS + r) * rowstr + h * 64 + c4;
                kr[i] = *(const float4*)&g_qkv[base + D_MODEL];
                vr[i] = *(const float4*)&g_qkv[base + 2 * D_MODEL];
            }
        }

        __syncthreads();

#pragma unroll 2
        for (int s = 0; s < TS; s++) {
            const float* pr = Ps + s * P_STR + (ty << 3);
            float4 p0 = *(const float4*)pr;
            float4 p1 = *(const float4*)(pr + 4);
            float4 v  = *(const float4*)&Vs[s * V_STR + (tx << 2)];
            float pv[8];
            pv[0] = p0.x; pv[1] = p0.y; pv[2] = p0.z; pv[3] = p0.w;
            pv[4] = p1.x; pv[5] = p1.y; pv[6] = p1.z; pv[7] = p1.w;
#pragma unroll
            for (int i = 0; i < 8; i++) {
                acc_o[i].x += pv[i] * v.x;
                acc_o[i].y += pv[i] * v.y;
                acc_o[i].z += pv[i] * v.z;
                acc_o[i].w += pv[i] * v.w;
            }
        }
    }

#pragma unroll
    for (int i = 0; i < 8; i++) {
        float inv = 1.f / l_i[i];
        float o0 = acc_o[i].x * inv;
        float o1 = acc_o[i].y * inv;
        float o2 = acc_o[i].z * inv;
        float o3 = acc_o[i].w * inv;
        size_t row = (size_t)(b * T_SEQ + q0 + (ty << 3) + i);
        size_t off = row * D_MODEL + h * 64 + (tx << 2);
        float h0 = __bfloat162float(__float2bfloat16(o0));
        float h1 = __bfloat162float(__float2bfloat16(o1));
        float h2 = __bfloat162float(__float2bfloat16(o2));
        float h3 = __bfloat162float(__float2bfloat16(o3));
        *(__nv_bfloat162*)&g_ah[off]     = __floats2bfloat162_rn(h0, h1);
        *(__nv_bfloat162*)&g_ah[off + 2] = __floats2bfloat162_rn(h2, h3);
        *(__nv_bfloat162*)&g_al[off]     = __floats2bfloat162_rn(o0 - h0, o1 - h1);
        *(__nv_bfloat162*)&g_al[off + 2] = __floats2bfloat162_rn(o2 - h2, o3 - h3);
    }
}

// ---------------------------------------------------------------------------
extern "C" void kernel_launch(void* const* d_in, const int* in_sizes, int n_in,
                              void* d_out, int out_size)
{
    const float* x      = (const float*)d_in[0];
    const float* qkv_w  = (const float*)d_in[1];
    const float* qkv_b  = (const float*)d_in[2];
    const float* out_w  = (const float*)d_in[3];
    const float* out_b  = (const float*)d_in[4];
    float* out = (float*)d_out;

    float* qkv_buf;
    __nv_bfloat16* xh;
    __nv_bfloat16* xl;
    __nv_bfloat16* wqh;
    __nv_bfloat16* wql;
    __nv_bfloat16* woh;
    __nv_bfloat16* wol;
    __nv_bfloat16* ah;
    __nv_bfloat16* al;
    cudaGetSymbolAddress((void**)&qkv_buf, g_qkv);
    cudaGetSymbolAddress((void**)&xh,  g_xh);
    cudaGetSymbolAddress((void**)&xl,  g_xl);
    cudaGetSymbolAddress((void**)&wqh, g_wqh);
    cudaGetSymbolAddress((void**)&wql, g_wql);
    cudaGetSymbolAddress((void**)&woh, g_woh);
    cudaGetSymbolAddress((void**)&wol, g_wol);
    cudaGetSymbolAddress((void**)&ah,  g_ah);
    cudaGetSymbolAddress((void**)&al,  g_al);

    const int smem_attn = SMEM_FLOATS * (int)sizeof(float);
    cudaFuncSetAttribute(attn_kernel,
                         cudaFuncAttributeMaxDynamicSharedMemorySize, smem_attn);

    int n4 = MTOT * D_MODEL / 4;
    split_kernel<<<(n4 + 255) / 256, 256>>>(x, xh, xl, n4);
    n4 = 3 * D_MODEL * D_MODEL / 4;
    split_kernel<<<(n4 + 255) / 256, 256>>>(qkv_w, wqh, wql, n4);
    n4 = D_MODEL * D_MODEL / 4;
    split_kernel<<<(n4 + 255) / 256, 256>>>(out_w, woh, wol, n4);

    {
        dim3 grid(3 * D_MODEL / 128, MTOT / 128);
        gemm_bf16x3<<<grid, 256>>>(xh, xl, wqh, wql, qkv_b, qkv_buf, 3 * D_MODEL);
    }
    {
        dim3 grid(T_SEQ / TQ, N_HEAD, BATCH);
        attn_kernel<<<grid, 256, smem_attn>>>();
    }
    {
        dim3 grid(D_MODEL / 128, MTOT / 128);
        gemm_bf16x3<<<grid, 256>>>(ah, al, woh, wol, out_b, out, D_MODEL);
    }
}

// round 5
// speedup vs baseline: 7.4087x; 1.7401x over previous
#include <cuda_runtime.h>
#include <cuda_bf16.h>
#include <math.h>

#define D_MODEL 1024
#define N_HEAD  16
#define T_SEQ   2048
#define BATCH   2
#define MTOT    4096
#define KDIM    1024
#define NSTEPS  192

__device__ float         g_qkv[(size_t)MTOT * 3 * D_MODEL];
__device__ __nv_bfloat16 g_xh [(size_t)MTOT * D_MODEL];
__device__ __nv_bfloat16 g_xl [(size_t)MTOT * D_MODEL];
__device__ __nv_bfloat16 g_wqh[(size_t)3 * D_MODEL * D_MODEL];
__device__ __nv_bfloat16 g_wql[(size_t)3 * D_MODEL * D_MODEL];
__device__ __nv_bfloat16 g_woh[(size_t)D_MODEL * D_MODEL];
__device__ __nv_bfloat16 g_wol[(size_t)D_MODEL * D_MODEL];
__device__ __nv_bfloat16 g_ah [(size_t)MTOT * D_MODEL];
__device__ __nv_bfloat16 g_al [(size_t)MTOT * D_MODEL];

__device__ __forceinline__ unsigned int bpack(float a, float b)
{
    __nv_bfloat162 p = __floats2bfloat162_rn(a, b);
    return *(unsigned int*)&p;
}

// fp32 -> bf16 hi/lo split
__global__ void split_kernel(const float* __restrict__ in,
                             __nv_bfloat16* __restrict__ hi,
                             __nv_bfloat16* __restrict__ lo, int n4)
{
    int i = blockIdx.x * blockDim.x + threadIdx.x;
    if (i >= n4) return;
    float4 v = ((const float4*)in)[i];
    float hx = __bfloat162float(__float2bfloat16(v.x));
    float hy = __bfloat162float(__float2bfloat16(v.y));
    float hz = __bfloat162float(__float2bfloat16(v.z));
    float hw = __bfloat162float(__float2bfloat16(v.w));
    ((__nv_bfloat162*)hi)[2 * i]     = __floats2bfloat162_rn(hx, hy);
    ((__nv_bfloat162*)hi)[2 * i + 1] = __floats2bfloat162_rn(hz, hw);
    ((__nv_bfloat162*)lo)[2 * i]     = __floats2bfloat162_rn(v.x - hx, v.y - hy);
    ((__nv_bfloat162*)lo)[2 * i + 1] = __floats2bfloat162_rn(v.z - hz, v.w - hw);
}

// ---------------------------------------------------------------------------
// mma helpers
// ---------------------------------------------------------------------------
__device__ __forceinline__ void cp16(unsigned int s, const void* g)
{
    asm volatile("cp.async.cg.shared.global [%0], [%1], 16;" :: "r"(s), "l"(g));
}
__device__ __forceinline__ void ldsm4(unsigned int* r, unsigned int a)
{
    asm volatile("ldmatrix.sync.aligned.m8n8.x4.shared.b16 {%0,%1,%2,%3}, [%4];"
                 : "=r"(r[0]), "=r"(r[1]), "=r"(r[2]), "=r"(r[3]) : "r"(a));
}
__device__ __forceinline__ void ldsm4t(unsigned int* r, unsigned int a)
{
    asm volatile("ldmatrix.sync.aligned.m8n8.x4.trans.shared.b16 {%0,%1,%2,%3}, [%4];"
                 : "=r"(r[0]), "=r"(r[1]), "=r"(r[2]), "=r"(r[3]) : "r"(a));
}
__device__ __forceinline__ void mma16816(float* c,
                                         const unsigned int* a,
                                         unsigned int e0, unsigned int e1)
{
    asm volatile(
        "mma.sync.aligned.m16n8k16.row.col.f32.bf16.bf16.f32 "
        "{%0,%1,%2,%3},{%4,%5,%6,%7},{%8,%9},{%0,%1,%2,%3};"
        : "+f"(c[0]), "+f"(c[1]), "+f"(c[2]), "+f"(c[3])
        : "r"(a[0]), "r"(a[1]), "r"(a[2]), "r"(a[3]), "r"(e0), "r"(e1));
}

// ---------------------------------------------------------------------------
// Tensor-core projection GEMM (proven, round 4)
// ---------------------------------------------------------------------------
#define GPITCH 24
#define GBUFB  (128 * GPITCH * 2)

__global__ __launch_bounds__(256, 2) void gemm_bf16x3(
    const __nv_bfloat16* __restrict__ Ah, const __nv_bfloat16* __restrict__ Al,
    const __nv_bfloat16* __restrict__ Bh, const __nv_bfloat16* __restrict__ Bl,
    const float* __restrict__ bias, float* __restrict__ C, int N)
{
    __shared__ __nv_bfloat16 sA[2][128 * GPITCH];
    __shared__ __nv_bfloat16 sB[2][128 * GPITCH];

    const int t    = threadIdx.x;
    const int lane = t & 31;
    const int warp = t >> 5;
    const int wm   = warp & 1;
    const int wn   = warp >> 1;
    const int m0   = blockIdx.y * 128;
    const int n0   = blockIdx.x * 128;

    const int ldrow = t >> 1;
    const int ldoff = (t & 1) * 8;

    const unsigned int sA0 = (unsigned int)__cvta_generic_to_shared(&sA[0][0]);
    const unsigned int sB0 = (unsigned int)__cvta_generic_to_shared(&sB[0][0]);
    const unsigned int a_st = sA0 + (unsigned int)(ldrow * GPITCH + ldoff) * 2u;
    const unsigned int b_st = sB0 + (unsigned int)(ldrow * GPITCH + ldoff) * 2u;
    const unsigned int a_ld = sA0 +
        (unsigned int)((wm * 64 + (lane & 15)) * GPITCH + (lane >> 4) * 8) * 2u;
    const unsigned int b_ld = sB0 +
        (unsigned int)((wn * 32 + (lane & 15)) * GPITCH + (lane >> 4) * 8) * 2u;

    float acc[4][4][4];
#pragma unroll
    for (int i = 0; i < 4; i++)
#pragma unroll
        for (int j = 0; j < 4; j++)
#pragma unroll
            for (int r = 0; r < 4; r++) acc[i][j][r] = 0.f;

    {
        const __nv_bfloat16* ga = Ah + (size_t)(m0 + ldrow) * KDIM + ldoff;
        const __nv_bfloat16* gb = Bh + (size_t)(n0 + ldrow) * KDIM + ldoff;
        cp16(a_st, ga);
        cp16(b_st, gb);
        asm volatile("cp.async.commit_group;");
    }

    for (int s = 0; s < NSTEPS; s++) {
        const int cur = s & 1;
        if (s + 1 < NSTEPS) {
            const int sn = s + 1;
            const int p  = sn >> 6;
            const int kk = (sn & 63) << 4;
            const __nv_bfloat16* pa = (p == 2) ? Al : Ah;
            const __nv_bfloat16* pb = (p == 1) ? Bl : Bh;
            const __nv_bfloat16* ga = pa + (size_t)(m0 + ldrow) * KDIM + kk + ldoff;
            const __nv_bfloat16* gb = pb + (size_t)(n0 + ldrow) * KDIM + kk + ldoff;
            const unsigned int off = (unsigned int)((cur ^ 1) * GBUFB);
            cp16(a_st + off, ga);
            cp16(b_st + off, gb);
            asm volatile("cp.async.commit_group;");
            asm volatile("cp.async.wait_group 1;");
        } else {
            asm volatile("cp.async.wait_group 0;");
        }
        __syncthreads();

        const unsigned int coff = (unsigned int)(cur * GBUFB);
        unsigned int fa[4][4];
#pragma unroll
        for (int mf = 0; mf < 4; mf++)
            ldsm4(fa[mf], a_ld + coff + (unsigned int)(mf * 16 * GPITCH * 2));
        unsigned int fb[2][4];
#pragma unroll
        for (int pf = 0; pf < 2; pf++)
            ldsm4(fb[pf], b_ld + coff + (unsigned int)(pf * 16 * GPITCH * 2));

#pragma unroll
        for (int mf = 0; mf < 4; mf++) {
#pragma unroll
            for (int pf = 0; pf < 2; pf++) {
                mma16816(acc[mf][2 * pf + 0], fa[mf], fb[pf][0], fb[pf][2]);
                mma16816(acc[mf][2 * pf + 1], fa[mf], fb[pf][1], fb[pf][3]);
            }
        }
        __syncthreads();
    }

    const int gr = lane >> 2;
    const int gc = (lane & 3) * 2;
#pragma unroll
    for (int mf = 0; mf < 4; mf++) {
#pragma unroll
        for (int nf = 0; nf < 4; nf++) {
            int m = m0 + wm * 64 + mf * 16 + gr;
            int n = n0 + wn * 32 + nf * 8 + gc;
            float b0 = bias[n];
            float b1 = bias[n + 1];
            float2 v0;
            v0.x = acc[mf][nf][0] + b0;
            v0.y = acc[mf][nf][1] + b1;
            float2 v1;
            v1.x = acc[mf][nf][2] + b0;
            v1.y = acc[mf][nf][3] + b1;
            *(float2*)&C[(size_t)m * N + n]       = v0;
            *(float2*)&C[(size_t)(m + 8) * N + n] = v1;
        }
    }
}

// ---------------------------------------------------------------------------
// Tensor-core flash attention, bf16x3 emulated fp32.
// Block = 256 threads (8 warps), one (b, h, 128-q tile).
// Warp w owns q rows w*16..w*16+15. S tiles of 128.
// Q frags (hi/lo) live in registers the whole kernel.
// K smem [s][dk] hi/lo (non-trans ldmatrix = B operand for QK^T).
// V smem [s][d] hi/lo (ldmatrix.trans = B operand for PV).
// P frags packed register-direct from score accumulators (hi/lo).
// ---------------------------------------------------------------------------
#define APITCH 72
#define ATT_SMEM (4 * 128 * APITCH * 2)

__global__ __launch_bounds__(256, 1) void attn_tc_kernel()
{
    extern __shared__ __nv_bfloat16 smb[];
    __nv_bfloat16* Kh = smb;
    __nv_bfloat16* Kl = Kh + 128 * APITCH;
    __nv_bfloat16* Vh = Kl + 128 * APITCH;
    __nv_bfloat16* Vl = Vh + 128 * APITCH;

    const int t    = threadIdx.x;
    const int lane = t & 31;
    const int w    = t >> 5;
    const int b    = blockIdx.z;
    const int h    = blockIdx.y;
    const int q0   = blockIdx.x * 128;
    const int rowstr = 3 * D_MODEL;
    const int gr   = lane >> 2;
    const int gc   = lane & 3;

    const unsigned int KhS = (unsigned int)__cvta_generic_to_shared(Kh);
    const unsigned int KlS = (unsigned int)__cvta_generic_to_shared(Kl);
    const unsigned int VhS = (unsigned int)__cvta_generic_to_shared(Vh);
    const unsigned int VlS = (unsigned int)__cvta_generic_to_shared(Vl);

    // ---- stage Q (scaled) into Kh/Kl, pull frags to registers ----
#pragma unroll
    for (int i = 0; i < 8; i++) {
        int slot = i * 256 + t;
        int r  = slot >> 4;
        int c4 = (slot & 15) << 2;
        float4 v = *(const float4*)
            &g_qkv[(size_t)(b * T_SEQ + q0 + r) * rowstr + h * 64 + c4];
        v.x *= 0.125f; v.y *= 0.125f; v.z *= 0.125f; v.w *= 0.125f;
        float hx = __bfloat162float(__float2bfloat16(v.x));
        float hy = __bfloat162float(__float2bfloat16(v.y));
        float hz = __bfloat162float(__float2bfloat16(v.z));
        float hw = __bfloat162float(__float2bfloat16(v.w));
        int o2 = r * APITCH + c4;
        *(__nv_bfloat162*)&Kh[o2]     = __floats2bfloat162_rn(hx, hy);
        *(__nv_bfloat162*)&Kh[o2 + 2] = __floats2bfloat162_rn(hz, hw);
        *(__nv_bfloat162*)&Kl[o2]     = __floats2bfloat162_rn(v.x - hx, v.y - hy);
        *(__nv_bfloat162*)&Kl[o2 + 2] = __floats2bfloat162_rn(v.z - hz, v.w - hw);
    }
    __syncthreads();

    unsigned int qh[4][4];
    unsigned int ql[4][4];
    {
        const unsigned int qoff =
            (unsigned int)((w * 16 + (lane & 15)) * APITCH + (lane >> 4) * 8) * 2u;
#pragma unroll
        for (int kc = 0; kc < 4; kc++) {
            ldsm4(qh[kc], KhS + qoff + (unsigned int)(kc * 32));
            ldsm4(ql[kc], KlS + qoff + (unsigned int)(kc * 32));
        }
    }
    __syncthreads();

    float sc[16][4];
    float o[8][4];
#pragma unroll
    for (int nf = 0; nf < 8; nf++)
#pragma unroll
        for (int r = 0; r < 4; r++) o[nf][r] = 0.f;
    float m0 = -1e30f, m1 = -1e30f, l0 = 0.f, l1 = 0.f;

    const unsigned int kfoff =
        (unsigned int)(((lane & 15)) * APITCH + (lane >> 4) * 8) * 2u;
    const unsigned int vfoff = kfoff;

    for (int s0 = 0; s0 < T_SEQ; s0 += 128) {
        // ---- load + split K and V tile ----
#pragma unroll
        for (int i = 0; i < 8; i++) {
            int slot = i * 256 + t;
            int r  = slot >> 4;
            int c4 = (slot & 15) << 2;
            size_t base = (size_t)(b * T_SEQ + s0 + r) * rowstr + h * 64 + c4;
            float4 kv = *(const float4*)&g_qkv[base + D_MODEL];
            float4 vv = *(const float4*)&g_qkv[base + 2 * D_MODEL];
            int o2 = r * APITCH + c4;
            float hx = __bfloat162float(__float2bfloat16(kv.x));
            float hy = __bfloat162float(__float2bfloat16(kv.y));
            float hz = __bfloat162float(__float2bfloat16(kv.z));
            float hw = __bfloat162float(__float2bfloat16(kv.w));
            *(__nv_bfloat162*)&Kh[o2]     = __floats2bfloat162_rn(hx, hy);
            *(__nv_bfloat162*)&Kh[o2 + 2] = __floats2bfloat162_rn(hz, hw);
            *(__nv_bfloat162*)&Kl[o2]     = __floats2bfloat162_rn(kv.x - hx, kv.y - hy);
            *(__nv_bfloat162*)&Kl[o2 + 2] = __floats2bfloat162_rn(kv.z - hz, kv.w - hw);
            hx = __bfloat162float(__float2bfloat16(vv.x));
            hy = __bfloat162float(__float2bfloat16(vv.y));
            hz = __bfloat162float(__float2bfloat16(vv.z));
            hw = __bfloat162float(__float2bfloat16(vv.w));
            *(__nv_bfloat162*)&Vh[o2]     = __floats2bfloat162_rn(hx, hy);
            *(__nv_bfloat162*)&Vh[o2 + 2] = __floats2bfloat162_rn(hz, hw);
            *(__nv_bfloat162*)&Vl[o2]     = __floats2bfloat162_rn(vv.x - hx, vv.y - hy);
            *(__nv_bfloat162*)&Vl[o2 + 2] = __floats2bfloat162_rn(vv.z - hz, vv.w - hw);
        }
        __syncthreads();

        // ---- QK^T: 128 q x 128 s ----
#pragma unroll
        for (int nf = 0; nf < 16; nf++)
#pragma unroll
            for (int r = 0; r < 4; r++) sc[nf][r] = 0.f;

#pragma unroll
        for (int ng = 0; ng < 8; ng++) {
            const unsigned int roff = (unsigned int)(ng * 16 * APITCH * 2);
#pragma unroll
            for (int kc = 0; kc < 4; kc++) {
                unsigned int kbh[4];
                unsigned int kbl[4];
                ldsm4(kbh, KhS + kfoff + roff + (unsigned int)(kc * 32));
                ldsm4(kbl, KlS + kfoff + roff + (unsigned int)(kc * 32));
                mma16816(sc[2 * ng],     qh[kc], kbh[0], kbh[2]);
                mma16816(sc[2 * ng + 1], qh[kc], kbh[1], kbh[3]);
                mma16816(sc[2 * ng],     qh[kc], kbl[0], kbl[2]);
                mma16816(sc[2 * ng + 1], qh[kc], kbl[1], kbl[3]);
                mma16816(sc[2 * ng],     ql[kc], kbh[0], kbh[2]);
                mma16816(sc[2 * ng + 1], ql[kc], kbh[1], kbh[3]);
            }
        }

        // ---- online softmax (rows gr and gr+8 of warp tile) ----
        float mx0 = -1e30f, mx1 = -1e30f;
#pragma unroll
        for (int nf = 0; nf < 16; nf++) {
            mx0 = fmaxf(mx0, fmaxf(sc[nf][0], sc[nf][1]));
            mx1 = fmaxf(mx1, fmaxf(sc[nf][2], sc[nf][3]));
        }
        mx0 = fmaxf(mx0, __shfl_xor_sync(0xffffffffu, mx0, 1));
        mx0 = fmaxf(mx0, __shfl_xor_sync(0xffffffffu, mx0, 2));
        mx1 = fmaxf(mx1, __shfl_xor_sync(0xffffffffu, mx1, 1));
        mx1 = fmaxf(mx1, __shfl_xor_sync(0xffffffffu, mx1, 2));
        float mn0 = fmaxf(m0, mx0);
        float mn1 = fmaxf(m1, mx1);
        float c0 = __expf(m0 - mn0);
        float c1 = __expf(m1 - mn1);
        m0 = mn0; m1 = mn1;
        float ls0 = 0.f, ls1 = 0.f;
#pragma unroll
        for (int nf = 0; nf < 16; nf++) {
            sc[nf][0] = __expf(sc[nf][0] - mn0);
            sc[nf][1] = __expf(sc[nf][1] - mn0);
            sc[nf][2] = __expf(sc[nf][2] - mn1);
            sc[nf][3] = __expf(sc[nf][3] - mn1);
            ls0 += sc[nf][0] + sc[nf][1];
            ls1 += sc[nf][2] + sc[nf][3];
        }
        ls0 += __shfl_xor_sync(0xffffffffu, ls0, 1);
        ls0 += __shfl_xor_sync(0xffffffffu, ls0, 2);
        ls1 += __shfl_xor_sync(0xffffffffu, ls1, 1);
        ls1 += __shfl_xor_sync(0xffffffffu, ls1, 2);
        l0 = l0 * c0 + ls0;
        l1 = l1 * c1 + ls1;
#pragma unroll
        for (int nf = 0; nf < 8; nf++) {
            o[nf][0] *= c0; o[nf][1] *= c0;
            o[nf][2] *= c1; o[nf][3] *= c1;
        }

        // ---- PV: P (register frags from sc) x V ----
#pragma unroll
        for (int kc = 0; kc < 8; kc++) {
            float v00 = sc[2 * kc][0],     v01 = sc[2 * kc][1];
            float v10 = sc[2 * kc][2],     v11 = sc[2 * kc][3];
            float v20 = sc[2 * kc + 1][0], v21 = sc[2 * kc + 1][1];
            float v30 = sc[2 * kc + 1][2], v31 = sc[2 * kc + 1][3];
            float h00 = __bfloat162float(__float2bfloat16(v00));
            float h01 = __bfloat162float(__float2bfloat16(v01));
            float h10 = __bfloat162float(__float2bfloat16(v10));
            float h11 = __bfloat162float(__float2bfloat16(v11));
            float h20 = __bfloat162float(__float2bfloat16(v20));
            float h21 = __bfloat162float(__float2bfloat16(v21));
            float h30 = __bfloat162float(__float2bfloat16(v30));
            float h31 = __bfloat162float(__float2bfloat16(v31));
            unsigned int pa_h[4];
            unsigned int pa_l[4];
            pa_h[0] = bpack(h00, h01);
            pa_h[1] = bpack(h10, h11);
            pa_h[2] = bpack(h20, h21);
            pa_h[3] = bpack(h30, h31);
            pa_l[0] = bpack(v00 - h00, v01 - h01);
            pa_l[1] = bpack(v10 - h10, v11 - h11);
            pa_l[2] = bpack(v20 - h20, v21 - h21);
            pa_l[3] = bpack(v30 - h30, v31 - h31);

            const unsigned int soff = (unsigned int)(kc * 16 * APITCH * 2);
#pragma unroll
            for (int dg = 0; dg < 4; dg++) {
                unsigned int vbh[4];
                unsigned int vbl[4];
                ldsm4t(vbh, VhS + vfoff + soff + (unsigned int)(dg * 32));
                ldsm4t(vbl, VlS + vfoff + soff + (unsigned int)(dg * 32));
                mma16816(o[2 * dg],     pa_h, vbh[0], vbh[1]);
                mma16816(o[2 * dg + 1], pa_h, vbh[2], vbh[3]);
                mma16816(o[2 * dg],     pa_h, vbl[0], vbl[1]);
                mma16816(o[2 * dg + 1], pa_h, vbl[2], vbl[3]);
                mma16816(o[2 * dg],     pa_l, vbh[0], vbh[1]);
                mma16816(o[2 * dg + 1], pa_l, vbh[2], vbh[3]);
            }
        }
        __syncthreads();
    }

    // ---- epilogue: divide by l, write bf16 hi/lo split ----
    float inv0 = 1.f / l0;
    float inv1 = 1.f / l1;
    const int row0 = q0 + w * 16 + gr;
    const int row1 = row0 + 8;
#pragma unroll
    for (int nf = 0; nf < 8; nf++) {
        int d = nf * 8 + 2 * gc;
        float a0 = o[nf][0] * inv0;
        float a1 = o[nf][1] * inv0;
        float b0v = o[nf][2] * inv1;
        float b1v = o[nf][3] * inv1;
        size_t off0 = (size_t)(b * T_SEQ + row0) * D_MODEL + h * 64 + d;
        size_t off1 = (size_t)(b * T_SEQ + row1) * D_MODEL + h * 64 + d;
        float ha0 = __bfloat162float(__float2bfloat16(a0));
        float ha1 = __bfloat162float(__float2bfloat16(a1));
        float hb0 = __bfloat162float(__float2bfloat16(b0v));
        float hb1 = __bfloat162float(__float2bfloat16(b1v));
        *(__nv_bfloat162*)&g_ah[off0] = __floats2bfloat162_rn(ha0, ha1);
        *(__nv_bfloat162*)&g_al[off0] = __floats2bfloat162_rn(a0 - ha0, a1 - ha1);
        *(__nv_bfloat162*)&g_ah[off1] = __floats2bfloat162_rn(hb0, hb1);
        *(__nv_bfloat162*)&g_al[off1] = __floats2bfloat162_rn(b0v - hb0, b1v - hb1);
    }
}

// ---------------------------------------------------------------------------
extern "C" void kernel_launch(void* const* d_in, const int* in_sizes, int n_in,
                              void* d_out, int out_size)
{
    const float* x      = (const float*)d_in[0];
    const float* qkv_w  = (const float*)d_in[1];
    const float* qkv_b  = (const float*)d_in[2];
    const float* out_w  = (const float*)d_in[3];
    const float* out_b  = (const float*)d_in[4];
    float* out = (float*)d_out;

    float* qkv_buf;
    __nv_bfloat16* xh;
    __nv_bfloat16* xl;
    __nv_bfloat16* wqh;
    __nv_bfloat16* wql;
    __nv_bfloat16* woh;
    __nv_bfloat16* wol;
    __nv_bfloat16* ah;
    __nv_bfloat16* al;
    cudaGetSymbolAddress((void**)&qkv_buf, g_qkv);
    cudaGetSymbolAddress((void**)&xh,  g_xh);
    cudaGetSymbolAddress((void**)&xl,  g_xl);
    cudaGetSymbolAddress((void**)&wqh, g_wqh);
    cudaGetSymbolAddress((void**)&wql, g_wql);
    cudaGetSymbolAddress((void**)&woh, g_woh);
    cudaGetSymbolAddress((void**)&wol, g_wol);
    cudaGetSymbolAddress((void**)&ah,  g_ah);
    cudaGetSymbolAddress((void**)&al,  g_al);

    cudaFuncSetAttribute(attn_tc_kernel,
                         cudaFuncAttributeMaxDynamicSharedMemorySize, ATT_SMEM);

    int n4 = MTOT * D_MODEL / 4;
    split_kernel<<<(n4 + 255) / 256, 256>>>(x, xh, xl, n4);
    n4 = 3 * D_MODEL * D_MODEL / 4;
    split_kernel<<<(n4 + 255) / 256, 256>>>(qkv_w, wqh, wql, n4);
    n4 = D_MODEL * D_MODEL / 4;
    split_kernel<<<(n4 + 255) / 256, 256>>>(out_w, woh, wol, n4);

    {
        dim3 grid(3 * D_MODEL / 128, MTOT / 128);
        gemm_bf16x3<<<grid, 256>>>(xh, xl, wqh, wql, qkv_b, qkv_buf, 3 * D_MODEL);
    }
    {
        dim3 grid(T_SEQ / 128, N_HEAD, BATCH);
        attn_tc_kernel<<<grid, 256, ATT_SMEM>>>();
    }
    {
        dim3 grid(D_MODEL / 128, MTOT / 128);
        gemm_bf16x3<<<grid, 256>>>(ah, al, woh, wol, out_b, out, D_MODEL);
    }
}

// round 6
// speedup vs baseline: 8.4532x; 1.1410x over previous
#include <cuda_runtime.h>
#include <cuda_bf16.h>
#include <math.h>

#define D_MODEL 1024
#define N_HEAD  16
#define T_SEQ   2048
#define BATCH   2
#define MTOT    4096
#define KDIM    1024

typedef __nv_bfloat16 bf16;

__device__ bf16 g_qh [(size_t)MTOT * 3 * D_MODEL];
__device__ bf16 g_ql [(size_t)MTOT * 3 * D_MODEL];
__device__ bf16 g_xh [(size_t)MTOT * D_MODEL];
__device__ bf16 g_xl [(size_t)MTOT * D_MODEL];
__device__ bf16 g_wqh[(size_t)3 * D_MODEL * D_MODEL];
__device__ bf16 g_wql[(size_t)3 * D_MODEL * D_MODEL];
__device__ bf16 g_woh[(size_t)D_MODEL * D_MODEL];
__device__ bf16 g_wol[(size_t)D_MODEL * D_MODEL];
__device__ bf16 g_ah [(size_t)MTOT * D_MODEL];
__device__ bf16 g_al [(size_t)MTOT * D_MODEL];

__device__ __forceinline__ unsigned int bpack(float a, float b)
{
    __nv_bfloat162 p = __floats2bfloat162_rn(a, b);
    return *(unsigned int*)&p;
}

__global__ void split_kernel(const float* __restrict__ in,
                             bf16* __restrict__ hi,
                             bf16* __restrict__ lo, int n4)
{
    int i = blockIdx.x * blockDim.x + threadIdx.x;
    if (i >= n4) return;
    float4 v = ((const float4*)in)[i];
    float hx = __bfloat162float(__float2bfloat16(v.x));
    float hy = __bfloat162float(__float2bfloat16(v.y));
    float hz = __bfloat162float(__float2bfloat16(v.z));
    float hw = __bfloat162float(__float2bfloat16(v.w));
    ((__nv_bfloat162*)hi)[2 * i]     = __floats2bfloat162_rn(hx, hy);
    ((__nv_bfloat162*)hi)[2 * i + 1] = __floats2bfloat162_rn(hz, hw);
    ((__nv_bfloat162*)lo)[2 * i]     = __floats2bfloat162_rn(v.x - hx, v.y - hy);
    ((__nv_bfloat162*)lo)[2 * i + 1] = __floats2bfloat162_rn(v.z - hz, v.w - hw);
}

__device__ __forceinline__ void cp16(unsigned int s, const void* g)
{
    asm volatile("cp.async.cg.shared.global [%0], [%1], 16;" :: "r"(s), "l"(g));
}
__device__ __forceinline__ void ldsm4(unsigned int* r, unsigned int a)
{
    asm volatile("ldmatrix.sync.aligned.m8n8.x4.shared.b16 {%0,%1,%2,%3}, [%4];"
                 : "=r"(r[0]), "=r"(r[1]), "=r"(r[2]), "=r"(r[3]) : "r"(a));
}
__device__ __forceinline__ void ldsm4t(unsigned int* r, unsigned int a)
{
    asm volatile("ldmatrix.sync.aligned.m8n8.x4.trans.shared.b16 {%0,%1,%2,%3}, [%4];"
                 : "=r"(r[0]), "=r"(r[1]), "=r"(r[2]), "=r"(r[3]) : "r"(a));
}
__device__ __forceinline__ void mma16816(float* c,
                                         const unsigned int* a,
                                         unsigned int e0, unsigned int e1)
{
    asm volatile(
        "mma.sync.aligned.m16n8k16.row.col.f32.bf16.bf16.f32 "
        "{%0,%1,%2,%3},{%4,%5,%6,%7},{%8,%9},{%0,%1,%2,%3};"
        : "+f"(c[0]), "+f"(c[1]), "+f"(c[2]), "+f"(c[3])
        : "r"(a[0]), "r"(a[1]), "r"(a[2]), "r"(a[3]), "r"(e0), "r"(e1));
}

// ---------------------------------------------------------------------------
// Fused 3-term bf16 GEMM: C = Ah@Bh^T + Ah@Bl^T + Al@Bh^T + bias.
// 64 k-steps (k=16 each), 3-stage cp.async, 4 tiles/stage.
// SPLIT=1: write hi/lo bf16 split of result; SPLIT=0: write fp32.
// ---------------------------------------------------------------------------
#define GP         24
#define GT_BYTES   (128 * GP * 2)     // 6144 per tile
#define GSTG_BYTES (4 * GT_BYTES)     // 24576 per stage
#define GSMEM      (3 * GSTG_BYTES)   // 73728

template<int SPLIT>
__global__ __launch_bounds__(256, 2) void gemm_fused(
    const bf16* __restrict__ Ah, const bf16* __restrict__ Al,
    const bf16* __restrict__ Bh, const bf16* __restrict__ Bl,
    const float* __restrict__ bias, float* __restrict__ C,
    bf16* __restrict__ Ch, bf16* __restrict__ Cl, int N)
{
    extern __shared__ bf16 gsm[];
    const unsigned int SBM = (unsigned int)__cvta_generic_to_shared(gsm);

    const int t    = threadIdx.x;
    const int lane = t & 31;
    const int warp = t >> 5;
    const int wm   = warp & 1;
    const int wn   = warp >> 1;
    const int m0   = blockIdx.y * 128;
    const int n0   = blockIdx.x * 128;
    const int ldrow = t >> 1;
    const int ldoff = (t & 1) * 8;

    const unsigned int st_b = (unsigned int)(ldrow * GP + ldoff) * 2u;
    const unsigned int a_fb = (unsigned int)((wm * 64 + (lane & 15)) * GP + (lane >> 4) * 8) * 2u;
    const unsigned int b_fb = (unsigned int)((wn * 32 + (lane & 15)) * GP + (lane >> 4) * 8) * 2u;

    const size_t arow = (size_t)(m0 + ldrow) * KDIM + ldoff;
    const size_t brow = (size_t)(n0 + ldrow) * KDIM + ldoff;

    float acc[4][4][4];
#pragma unroll
    for (int i = 0; i < 4; i++)
#pragma unroll
        for (int j = 0; j < 4; j++)
#pragma unroll
            for (int r = 0; r < 4; r++) acc[i][j][r] = 0.f;

    // prologue: stage tiles 0 and 1
#pragma unroll
    for (int s = 0; s < 2; s++) {
        unsigned int db = SBM + (unsigned int)(s * GSTG_BYTES) + st_b;
        int kk = s * 16;
        cp16(db,                Ah + arow + kk);
        cp16(db + GT_BYTES,     Al + arow + kk);
        cp16(db + 2 * GT_BYTES, Bh + brow + kk);
        cp16(db + 3 * GT_BYTES, Bl + brow + kk);
        asm volatile("cp.async.commit_group;");
    }

    int stg = 0;
    for (int s = 0; s < 64; s++) {
        if (s < 63) asm volatile("cp.async.wait_group 1;");
        else        asm volatile("cp.async.wait_group 0;");
        __syncthreads();

        const unsigned int sb = SBM + (unsigned int)(stg * GSTG_BYTES);
        unsigned int fah[4][4];
        unsigned int fal[4][4];
        unsigned int fbh[2][4];
        unsigned int fbl[2][4];
#pragma unroll
        for (int mf = 0; mf < 4; mf++) {
            ldsm4(fah[mf], sb + a_fb + (unsigned int)(mf * 16 * GP * 2));
            ldsm4(fal[mf], sb + GT_BYTES + a_fb + (unsigned int)(mf * 16 * GP * 2));
        }
#pragma unroll
        for (int pf = 0; pf < 2; pf++) {
            ldsm4(fbh[pf], sb + 2 * GT_BYTES + b_fb + (unsigned int)(pf * 16 * GP * 2));
            ldsm4(fbl[pf], sb + 3 * GT_BYTES + b_fb + (unsigned int)(pf * 16 * GP * 2));
        }

#pragma unroll
        for (int mf = 0; mf < 4; mf++) {
#pragma unroll
            for (int pf = 0; pf < 2; pf++) {
                mma16816(acc[mf][2 * pf],     fah[mf], fbh[pf][0], fbh[pf][2]);
                mma16816(acc[mf][2 * pf + 1], fah[mf], fbh[pf][1], fbh[pf][3]);
                mma16816(acc[mf][2 * pf],     fah[mf], fbl[pf][0], fbl[pf][2]);
                mma16816(acc[mf][2 * pf + 1], fah[mf], fbl[pf][1], fbl[pf][3]);
                mma16816(acc[mf][2 * pf],     fal[mf], fbh[pf][0], fbh[pf][2]);
                mma16816(acc[mf][2 * pf + 1], fal[mf], fbh[pf][1], fbh[pf][3]);
            }
        }

        if (s + 2 < 64) {
            int st2 = stg + 2;
            if (st2 >= 3) st2 -= 3;
            unsigned int db = SBM + (unsigned int)(st2 * GSTG_BYTES) + st_b;
            int kk = (s + 2) * 16;
            cp16(db,                Ah + arow + kk);
            cp16(db + GT_BYTES,     Al + arow + kk);
            cp16(db + 2 * GT_BYTES, Bh + brow + kk);
            cp16(db + 3 * GT_BYTES, Bl + brow + kk);
            asm volatile("cp.async.commit_group;");
        }
        stg++;
        if (stg == 3) stg = 0;
    }

    const int gr = lane >> 2;
    const int gc = (lane & 3) * 2;
#pragma unroll
    for (int mf = 0; mf < 4; mf++) {
#pragma unroll
        for (int nf = 0; nf < 4; nf++) {
            int m = m0 + wm * 64 + mf * 16 + gr;
            int n = n0 + wn * 32 + nf * 8 + gc;
            float b0 = bias[n];
            float b1 = bias[n + 1];
            float x0 = acc[mf][nf][0] + b0;
            float x1 = acc[mf][nf][1] + b1;
            float y0 = acc[mf][nf][2] + b0;
            float y1 = acc[mf][nf][3] + b1;
            if (SPLIT) {
                float hx0 = __bfloat162float(__float2bfloat16(x0));
                float hx1 = __bfloat162float(__float2bfloat16(x1));
                float hy0 = __bfloat162float(__float2bfloat16(y0));
                float hy1 = __bfloat162float(__float2bfloat16(y1));
                *(__nv_bfloat162*)&Ch[(size_t)m * N + n] =
                    __floats2bfloat162_rn(hx0, hx1);
                *(__nv_bfloat162*)&Cl[(size_t)m * N + n] =
                    __floats2bfloat162_rn(x0 - hx0, x1 - hx1);
                *(__nv_bfloat162*)&Ch[(size_t)(m + 8) * N + n] =
                    __floats2bfloat162_rn(hy0, hy1);
                *(__nv_bfloat162*)&Cl[(size_t)(m + 8) * N + n] =
                    __floats2bfloat162_rn(y0 - hy0, y1 - hy1);
            } else {
                float2 v0;
                v0.x = x0; v0.y = x1;
                float2 v1;
                v1.x = y0; v1.y = y1;
                *(float2*)&C[(size_t)m * N + n]       = v0;
                *(float2*)&C[(size_t)(m + 8) * N + n] = v1;
            }
        }
    }
}

// ---------------------------------------------------------------------------
// Tensor-core flash attention, bf16x3, cp.async double-buffered K/V tiles.
// K/V/Q come pre-split (hi/lo bf16) from GEMM1's epilogue.
// ---------------------------------------------------------------------------
#define AP         72
#define AT_BYTES   (128 * AP * 2)     // 18432 per tile
#define ASTG_BYTES (4 * AT_BYTES)     // 73728 per stage (Kh,Kl,Vh,Vl)
#define ASMEM      (2 * ASTG_BYTES)   // 147456

__device__ __forceinline__ void attn_issue_tile(unsigned int SBM, int stage,
                                                int tile, int b, int h, int t)
{
    const int rowstr = 3 * D_MODEL;
#pragma unroll
    for (int i = 0; i < 4; i++) {
        int slot = i * 256 + t;
        int r  = slot >> 3;
        int cc = (slot & 7) * 8;
        unsigned int d = SBM + (unsigned int)(stage * ASTG_BYTES)
                       + (unsigned int)((r * AP + cc) * 2);
        size_t base = (size_t)(b * T_SEQ + tile * 128 + r) * rowstr + h * 64 + cc;
        cp16(d,                g_qh + base + D_MODEL);
        cp16(d + AT_BYTES,     g_ql + base + D_MODEL);
        cp16(d + 2 * AT_BYTES, g_qh + base + 2 * D_MODEL);
        cp16(d + 3 * AT_BYTES, g_ql + base + 2 * D_MODEL);
    }
    asm volatile("cp.async.commit_group;");
}

__global__ __launch_bounds__(256, 1) void attn_tc_kernel()
{
    extern __shared__ bf16 smb[];
    const unsigned int SBM = (unsigned int)__cvta_generic_to_shared(smb);

    const int t    = threadIdx.x;
    const int lane = t & 31;
    const int w    = t >> 5;
    const int b    = blockIdx.z;
    const int h    = blockIdx.y;
    const int q0   = blockIdx.x * 128;
    const int rowstr = 3 * D_MODEL;
    const int gr   = lane >> 2;
    const int gc   = lane & 3;

    // ---- stage Q (hi/lo) into stage-0 K areas, pull frags ----
#pragma unroll
    for (int i = 0; i < 4; i++) {
        int slot = i * 256 + t;
        int r  = slot >> 3;
        int cc = (slot & 7) * 8;
        unsigned int d = SBM + (unsigned int)((r * AP + cc) * 2);
        size_t base = (size_t)(b * T_SEQ + q0 + r) * rowstr + h * 64 + cc;
        cp16(d,            g_qh + base);
        cp16(d + AT_BYTES, g_ql + base);
    }
    asm volatile("cp.async.commit_group;");
    asm volatile("cp.async.wait_group 0;");
    __syncthreads();

    unsigned int qfh[4][4];
    unsigned int qfl[4][4];
    {
        const unsigned int qoff =
            (unsigned int)((w * 16 + (lane & 15)) * AP + (lane >> 4) * 8) * 2u;
#pragma unroll
        for (int kc = 0; kc < 4; kc++) {
            ldsm4(qfh[kc], SBM + qoff + (unsigned int)(kc * 32));
            ldsm4(qfl[kc], SBM + AT_BYTES + qoff + (unsigned int)(kc * 32));
        }
    }
    __syncthreads();

    // prologue: tiles 0, 1
    attn_issue_tile(SBM, 0, 0, b, h, t);
    attn_issue_tile(SBM, 1, 1, b, h, t);

    float sc[16][4];
    float o[8][4];
#pragma unroll
    for (int nf = 0; nf < 8; nf++)
#pragma unroll
        for (int r = 0; r < 4; r++) o[nf][r] = 0.f;
    float rm0 = -1e30f, rm1 = -1e30f, rl0 = 0.f, rl1 = 0.f;

    const unsigned int kfoff =
        (unsigned int)((lane & 15) * AP + (lane >> 4) * 8) * 2u;

    for (int it = 0; it < 16; it++) {
        if (it < 15) asm volatile("cp.async.wait_group 1;");
        else         asm volatile("cp.async.wait_group 0;");
        __syncthreads();

        const unsigned int sb = SBM + (unsigned int)((it & 1) * ASTG_BYTES);

        // ---- QK^T ----
#pragma unroll
        for (int nf = 0; nf < 16; nf++)
#pragma unroll
            for (int r = 0; r < 4; r++) sc[nf][r] = 0.f;

#pragma unroll
        for (int ng = 0; ng < 8; ng++) {
            const unsigned int roff = (unsigned int)(ng * 16 * AP * 2);
#pragma unroll
            for (int kc = 0; kc < 4; kc++) {
                unsigned int kbh[4];
                unsigned int kbl[4];
                ldsm4(kbh, sb + kfoff + roff + (unsigned int)(kc * 32));
                ldsm4(kbl, sb + AT_BYTES + kfoff + roff + (unsigned int)(kc * 32));
                mma16816(sc[2 * ng],     qfh[kc], kbh[0], kbh[2]);
                mma16816(sc[2 * ng + 1], qfh[kc], kbh[1], kbh[3]);
                mma16816(sc[2 * ng],     qfh[kc], kbl[0], kbl[2]);
                mma16816(sc[2 * ng + 1], qfh[kc], kbl[1], kbl[3]);
                mma16816(sc[2 * ng],     qfl[kc], kbh[0], kbh[2]);
                mma16816(sc[2 * ng + 1], qfl[kc], kbh[1], kbh[3]);
            }
        }

        // ---- scale + online softmax ----
#pragma unroll
        for (int nf = 0; nf < 16; nf++) {
            sc[nf][0] *= 0.125f;
            sc[nf][1] *= 0.125f;
            sc[nf][2] *= 0.125f;
            sc[nf][3] *= 0.125f;
        }
        float mx0 = -1e30f, mx1 = -1e30f;
#pragma unroll
        for (int nf = 0; nf < 16; nf++) {
            mx0 = fmaxf(mx0, fmaxf(sc[nf][0], sc[nf][1]));
            mx1 = fmaxf(mx1, fmaxf(sc[nf][2], sc[nf][3]));
        }
        mx0 = fmaxf(mx0, __shfl_xor_sync(0xffffffffu, mx0, 1));
        mx0 = fmaxf(mx0, __shfl_xor_sync(0xffffffffu, mx0, 2));
        mx1 = fmaxf(mx1, __shfl_xor_sync(0xffffffffu, mx1, 1));
        mx1 = fmaxf(mx1, __shfl_xor_sync(0xffffffffu, mx1, 2));
        float mn0 = fmaxf(rm0, mx0);
        float mn1 = fmaxf(rm1, mx1);
        float c0 = __expf(rm0 - mn0);
        float c1 = __expf(rm1 - mn1);
        rm0 = mn0;
        rm1 = mn1;
        float ls0 = 0.f, ls1 = 0.f;
#pragma unroll
        for (int nf = 0; nf < 16; nf++) {
            sc[nf][0] = __expf(sc[nf][0] - mn0);
            sc[nf][1] = __expf(sc[nf][1] - mn0);
            sc[nf][2] = __expf(sc[nf][2] - mn1);
            sc[nf][3] = __expf(sc[nf][3] - mn1);
            ls0 += sc[nf][0] + sc[nf][1];
            ls1 += sc[nf][2] + sc[nf][3];
        }
        ls0 += __shfl_xor_sync(0xffffffffu, ls0, 1);
        ls0 += __shfl_xor_sync(0xffffffffu, ls0, 2);
        ls1 += __shfl_xor_sync(0xffffffffu, ls1, 1);
        ls1 += __shfl_xor_sync(0xffffffffu, ls1, 2);
        rl0 = rl0 * c0 + ls0;
        rl1 = rl1 * c1 + ls1;
#pragma unroll
        for (int nf = 0; nf < 8; nf++) {
            o[nf][0] *= c0;
            o[nf][1] *= c0;
            o[nf][2] *= c1;
            o[nf][3] *= c1;
        }

        // ---- PV ----
#pragma unroll
        for (int kc = 0; kc < 8; kc++) {
            float v00 = sc[2 * kc][0],     v01 = sc[2 * kc][1];
            float v10 = sc[2 * kc][2],     v11 = sc[2 * kc][3];
            float v20 = sc[2 * kc + 1][0], v21 = sc[2 * kc + 1][1];
            float v30 = sc[2 * kc + 1][2], v31 = sc[2 * kc + 1][3];
            float h00 = __bfloat162float(__float2bfloat16(v00));
            float h01 = __bfloat162float(__float2bfloat16(v01));
            float h10 = __bfloat162float(__float2bfloat16(v10));
            float h11 = __bfloat162float(__float2bfloat16(v11));
            float h20 = __bfloat162float(__float2bfloat16(v20));
            float h21 = __bfloat162float(__float2bfloat16(v21));
            float h30 = __bfloat162float(__float2bfloat16(v30));
            float h31 = __bfloat162float(__float2bfloat16(v31));
            unsigned int pa_h[4];
            unsigned int pa_l[4];
            pa_h[0] = bpack(h00, h01);
            pa_h[1] = bpack(h10, h11);
            pa_h[2] = bpack(h20, h21);
            pa_h[3] = bpack(h30, h31);
            pa_l[0] = bpack(v00 - h00, v01 - h01);
            pa_l[1] = bpack(v10 - h10, v11 - h11);
            pa_l[2] = bpack(v20 - h20, v21 - h21);
            pa_l[3] = bpack(v30 - h30, v31 - h31);

            const unsigned int soff = (unsigned int)(kc * 16 * AP * 2);
#pragma unroll
            for (int dg = 0; dg < 4; dg++) {
                unsigned int vbh[4];
                unsigned int vbl[4];
                ldsm4t(vbh, sb + 2 * AT_BYTES + kfoff + soff + (unsigned int)(dg * 32));
                ldsm4t(vbl, sb + 3 * AT_BYTES + kfoff + soff + (unsigned int)(dg * 32));
                mma16816(o[2 * dg],     pa_h, vbh[0], vbh[1]);
                mma16816(o[2 * dg + 1], pa_h, vbh[2], vbh[3]);
                mma16816(o[2 * dg],     pa_h, vbl[0], vbl[1]);
                mma16816(o[2 * dg + 1], pa_h, vbl[2], vbl[3]);
                mma16816(o[2 * dg],     pa_l, vbh[0], vbh[1]);
                mma16816(o[2 * dg + 1], pa_l, vbh[2], vbh[3]);
            }
        }
        __syncthreads();

        if (it + 2 < 16)
            attn_issue_tile(SBM, it & 1, it + 2, b, h, t);
    }

    // ---- epilogue ----
    float inv0 = 1.f / rl0;
    float inv1 = 1.f / rl1;
    const int row0 = q0 + w * 16 + gr;
    const int row1 = row0 + 8;
#pragma unroll
    for (int nf = 0; nf < 8; nf++) {
        int d = nf * 8 + 2 * gc;
        float a0 = o[nf][0] * inv0;
        float a1 = o[nf][1] * inv0;
        float b0v = o[nf][2] * inv1;
        float b1v = o[nf][3] * inv1;
        size_t off0 = (size_t)(b * T_SEQ + row0) * D_MODEL + h * 64 + d;
        size_t off1 = (size_t)(b * T_SEQ + row1) * D_MODEL + h * 64 + d;
        float ha0 = __bfloat162float(__float2bfloat16(a0));
        float ha1 = __bfloat162float(__float2bfloat16(a1));
        float hb0 = __bfloat162float(__float2bfloat16(b0v));
        float hb1 = __bfloat162float(__float2bfloat16(b1v));
        *(__nv_bfloat162*)&g_ah[off0] = __floats2bfloat162_rn(ha0, ha1);
        *(__nv_bfloat162*)&g_al[off0] = __floats2bfloat162_rn(a0 - ha0, a1 - ha1);
        *(__nv_bfloat162*)&g_ah[off1] = __floats2bfloat162_rn(hb0, hb1);
        *(__nv_bfloat162*)&g_al[off1] = __floats2bfloat162_rn(b0v - hb0, b1v - hb1);
    }
}

// ---------------------------------------------------------------------------
extern "C" void kernel_launch(void* const* d_in, const int* in_sizes, int n_in,
                              void* d_out, int out_size)
{
    const float* x      = (const float*)d_in[0];
    const float* qkv_w  = (const float*)d_in[1];
    const float* qkv_b  = (const float*)d_in[2];
    const float* out_w  = (const float*)d_in[3];
    const float* out_b  = (const float*)d_in[4];
    float* out = (float*)d_out;

    bf16* xh;  bf16* xl;
    bf16* wqh; bf16* wql;
    bf16* woh; bf16* wol;
    bf16* qh;  bf16* ql;
    bf16* ah;  bf16* al;
    cudaGetSymbolAddress((void**)&xh,  g_xh);
    cudaGetSymbolAddress((void**)&xl,  g_xl);
    cudaGetSymbolAddress((void**)&wqh, g_wqh);
    cudaGetSymbolAddress((void**)&wql, g_wql);
    cudaGetSymbolAddress((void**)&woh, g_woh);
    cudaGetSymbolAddress((void**)&wol, g_wol);
    cudaGetSymbolAddress((void**)&qh,  g_qh);
    cudaGetSymbolAddress((void**)&ql,  g_ql);
    cudaGetSymbolAddress((void**)&ah,  g_ah);
    cudaGetSymbolAddress((void**)&al,  g_al);

    cudaFuncSetAttribute(gemm_fused<1>,
                         cudaFuncAttributeMaxDynamicSharedMemorySize, GSMEM);
    cudaFuncSetAttribute(gemm_fused<0>,
                         cudaFuncAttributeMaxDynamicSharedMemorySize, GSMEM);
    cudaFuncSetAttribute(attn_tc_kernel,
                         cudaFuncAttributeMaxDynamicSharedMemorySize, ASMEM);

    int n4 = MTOT * D_MODEL / 4;
    split_kernel<<<(n4 + 255) / 256, 256>>>(x, xh, xl, n4);
    n4 = 3 * D_MODEL * D_MODEL / 4;
    split_kernel<<<(n4 + 255) / 256, 256>>>(qkv_w, wqh, wql, n4);
    n4 = D_MODEL * D_MODEL / 4;
    split_kernel<<<(n4 + 255) / 256, 256>>>(out_w, woh, wol, n4);

    {
        dim3 grid(3 * D_MODEL / 128, MTOT / 128);
        gemm_fused<1><<<grid, 256, GSMEM>>>(xh, xl, wqh, wql, qkv_b,
                                            (float*)0, qh, ql, 3 * D_MODEL);
    }
    {
        dim3 grid(T_SEQ / 128, N_HEAD, BATCH);
        attn_tc_kernel<<<grid, 256, ASMEM>>>();
    }
    {
        dim3 grid(D_MODEL / 128, MTOT / 128);
        gemm_fused<0><<<grid, 256, GSMEM>>>(ah, al, woh, wol, out_b,
                                            out, (bf16*)0, (bf16*)0, D_MODEL);
    }
}

// round 7
// speedup vs baseline: 8.4958x; 1.0050x over previous
#include <cuda_runtime.h>
#include <cuda_bf16.h>
#include <math.h>

#define D_MODEL 1024
#define N_HEAD  16
#define T_SEQ   2048
#define BATCH   2
#define MTOT    4096
#define KDIM    1024

typedef __nv_bfloat16 bf16;

__device__ bf16 g_qh [(size_t)MTOT * 3 * D_MODEL];
__device__ bf16 g_ql [(size_t)MTOT * 3 * D_MODEL];
__device__ bf16 g_xh [(size_t)MTOT * D_MODEL];
__device__ bf16 g_xl [(size_t)MTOT * D_MODEL];
__device__ bf16 g_wqh[(size_t)3 * D_MODEL * D_MODEL];
__device__ bf16 g_wql[(size_t)3 * D_MODEL * D_MODEL];
__device__ bf16 g_woh[(size_t)D_MODEL * D_MODEL];
__device__ bf16 g_wol[(size_t)D_MODEL * D_MODEL];
__device__ bf16 g_ah [(size_t)MTOT * D_MODEL];
__device__ bf16 g_al [(size_t)MTOT * D_MODEL];

__device__ __forceinline__ unsigned int bpack(float a, float b)
{
    __nv_bfloat162 p = __floats2bfloat162_rn(a, b);
    return *(unsigned int*)&p;
}

__global__ void split_kernel(const float* __restrict__ in,
                             bf16* __restrict__ hi,
                             bf16* __restrict__ lo, int n4)
{
    int i = blockIdx.x * blockDim.x + threadIdx.x;
    if (i >= n4) return;
    float4 v = ((const float4*)in)[i];
    float hx = __bfloat162float(__float2bfloat16(v.x));
    float hy = __bfloat162float(__float2bfloat16(v.y));
    float hz = __bfloat162float(__float2bfloat16(v.z));
    float hw = __bfloat162float(__float2bfloat16(v.w));
    ((__nv_bfloat162*)hi)[2 * i]     = __floats2bfloat162_rn(hx, hy);
    ((__nv_bfloat162*)hi)[2 * i + 1] = __floats2bfloat162_rn(hz, hw);
    ((__nv_bfloat162*)lo)[2 * i]     = __floats2bfloat162_rn(v.x - hx, v.y - hy);
    ((__nv_bfloat162*)lo)[2 * i + 1] = __floats2bfloat162_rn(v.z - hz, v.w - hw);
}

__device__ __forceinline__ void cp16(unsigned int s, const void* g)
{
    asm volatile("cp.async.cg.shared.global [%0], [%1], 16;" :: "r"(s), "l"(g));
}
__device__ __forceinline__ void ldsm4(unsigned int* r, unsigned int a)
{
    asm volatile("ldmatrix.sync.aligned.m8n8.x4.shared.b16 {%0,%1,%2,%3}, [%4];"
                 : "=r"(r[0]), "=r"(r[1]), "=r"(r[2]), "=r"(r[3]) : "r"(a));
}
__device__ __forceinline__ void ldsm4t(unsigned int* r, unsigned int a)
{
    asm volatile("ldmatrix.sync.aligned.m8n8.x4.trans.shared.b16 {%0,%1,%2,%3}, [%4];"
                 : "=r"(r[0]), "=r"(r[1]), "=r"(r[2]), "=r"(r[3]) : "r"(a));
}
__device__ __forceinline__ void mma16816(float* c,
                                         const unsigned int* a,
                                         unsigned int e0, unsigned int e1)
{
    asm volatile(
        "mma.sync.aligned.m16n8k16.row.col.f32.bf16.bf16.f32 "
        "{%0,%1,%2,%3},{%4,%5,%6,%7},{%8,%9},{%0,%1,%2,%3};"
        : "+f"(c[0]), "+f"(c[1]), "+f"(c[2]), "+f"(c[3])
        : "r"(a[0]), "r"(a[1]), "r"(a[2]), "r"(a[3]), "r"(e0), "r"(e1));
}

// ---------------------------------------------------------------------------
// Fused 3-term bf16 GEMM, term-major MMA issue (16-apart acc reuse).
// ---------------------------------------------------------------------------
#define GP         24
#define GT_BYTES   (128 * GP * 2)
#define GSTG_BYTES (4 * GT_BYTES)
#define GSMEM      (3 * GSTG_BYTES)

template<int SPLIT>
__global__ __launch_bounds__(256, 2) void gemm_fused(
    const bf16* __restrict__ Ah, const bf16* __restrict__ Al,
    const bf16* __restrict__ Bh, const bf16* __restrict__ Bl,
    const float* __restrict__ bias, float* __restrict__ C,
    bf16* __restrict__ Ch, bf16* __restrict__ Cl, int N)
{
    extern __shared__ bf16 gsm[];
    const unsigned int SBM = (unsigned int)__cvta_generic_to_shared(gsm);

    const int t    = threadIdx.x;
    const int lane = t & 31;
    const int warp = t >> 5;
    const int wm   = warp & 1;
    const int wn   = warp >> 1;
    const int m0   = blockIdx.y * 128;
    const int n0   = blockIdx.x * 128;
    const int ldrow = t >> 1;
    const int ldoff = (t & 1) * 8;

    const unsigned int st_b = (unsigned int)(ldrow * GP + ldoff) * 2u;
    const unsigned int a_fb = (unsigned int)((wm * 64 + (lane & 15)) * GP + (lane >> 4) * 8) * 2u;
    const unsigned int b_fb = (unsigned int)((wn * 32 + (lane & 15)) * GP + (lane >> 4) * 8) * 2u;

    const size_t arow = (size_t)(m0 + ldrow) * KDIM + ldoff;
    const size_t brow = (size_t)(n0 + ldrow) * KDIM + ldoff;

    float acc[4][4][4];
#pragma unroll
    for (int i = 0; i < 4; i++)
#pragma unroll
        for (int j = 0; j < 4; j++)
#pragma unroll
            for (int r = 0; r < 4; r++) acc[i][j][r] = 0.f;

#pragma unroll
    for (int s = 0; s < 2; s++) {
        unsigned int db = SBM + (unsigned int)(s * GSTG_BYTES) + st_b;
        int kk = s * 16;
        cp16(db,                Ah + arow + kk);
        cp16(db + GT_BYTES,     Al + arow + kk);
        cp16(db + 2 * GT_BYTES, Bh + brow + kk);
        cp16(db + 3 * GT_BYTES, Bl + brow + kk);
        asm volatile("cp.async.commit_group;");
    }

    int stg = 0;
    for (int s = 0; s < 64; s++) {
        if (s < 63) asm volatile("cp.async.wait_group 1;");
        else        asm volatile("cp.async.wait_group 0;");
        __syncthreads();

        const unsigned int sb = SBM + (unsigned int)(stg * GSTG_BYTES);
        unsigned int fah[4][4];
        unsigned int fal[4][4];
        unsigned int fbh[2][4];
        unsigned int fbl[2][4];
#pragma unroll
        for (int mf = 0; mf < 4; mf++) {
            ldsm4(fah[mf], sb + a_fb + (unsigned int)(mf * 16 * GP * 2));
            ldsm4(fal[mf], sb + GT_BYTES + a_fb + (unsigned int)(mf * 16 * GP * 2));
        }
#pragma unroll
        for (int pf = 0; pf < 2; pf++) {
            ldsm4(fbh[pf], sb + 2 * GT_BYTES + b_fb + (unsigned int)(pf * 16 * GP * 2));
            ldsm4(fbl[pf], sb + 3 * GT_BYTES + b_fb + (unsigned int)(pf * 16 * GP * 2));
        }

        // term-major: same-accumulator reuse distance = 16 MMAs
#pragma unroll
        for (int mf = 0; mf < 4; mf++)
#pragma unroll
            for (int pf = 0; pf < 2; pf++) {
                mma16816(acc[mf][2 * pf],     fah[mf], fbh[pf][0], fbh[pf][2]);
                mma16816(acc[mf][2 * pf + 1], fah[mf], fbh[pf][1], fbh[pf][3]);
            }
#pragma unroll
        for (int mf = 0; mf < 4; mf++)
#pragma unroll
            for (int pf = 0; pf < 2; pf++) {
                mma16816(acc[mf][2 * pf],     fah[mf], fbl[pf][0], fbl[pf][2]);
                mma16816(acc[mf][2 * pf + 1], fah[mf], fbl[pf][1], fbl[pf][3]);
            }
#pragma unroll
        for (int mf = 0; mf < 4; mf++)
#pragma unroll
            for (int pf = 0; pf < 2; pf++) {
                mma16816(acc[mf][2 * pf],     fal[mf], fbh[pf][0], fbh[pf][2]);
                mma16816(acc[mf][2 * pf + 1], fal[mf], fbh[pf][1], fbh[pf][3]);
            }

        if (s + 2 < 64) {
            int st2 = stg + 2;
            if (st2 >= 3) st2 -= 3;
            unsigned int db = SBM + (unsigned int)(st2 * GSTG_BYTES) + st_b;
            int kk = (s + 2) * 16;
            cp16(db,                Ah + arow + kk);
            cp16(db + GT_BYTES,     Al + arow + kk);
            cp16(db + 2 * GT_BYTES, Bh + brow + kk);
            cp16(db + 3 * GT_BYTES, Bl + brow + kk);
            asm volatile("cp.async.commit_group;");
        }
        stg++;
        if (stg == 3) stg = 0;
    }

    const int gr = lane >> 2;
    const int gc = (lane & 3) * 2;
#pragma unroll
    for (int mf = 0; mf < 4; mf++) {
#pragma unroll
        for (int nf = 0; nf < 4; nf++) {
            int m = m0 + wm * 64 + mf * 16 + gr;
            int n = n0 + wn * 32 + nf * 8 + gc;
            float b0 = bias[n];
            float b1 = bias[n + 1];
            float x0 = acc[mf][nf][0] + b0;
            float x1 = acc[mf][nf][1] + b1;
            float y0 = acc[mf][nf][2] + b0;
            float y1 = acc[mf][nf][3] + b1;
            if (SPLIT) {
                float hx0 = __bfloat162float(__float2bfloat16(x0));
                float hx1 = __bfloat162float(__float2bfloat16(x1));
                float hy0 = __bfloat162float(__float2bfloat16(y0));
                float hy1 = __bfloat162float(__float2bfloat16(y1));
                *(__nv_bfloat162*)&Ch[(size_t)m * N + n] =
                    __floats2bfloat162_rn(hx0, hx1);
                *(__nv_bfloat162*)&Cl[(size_t)m * N + n] =
                    __floats2bfloat162_rn(x0 - hx0, x1 - hx1);
                *(__nv_bfloat162*)&Ch[(size_t)(m + 8) * N + n] =
                    __floats2bfloat162_rn(hy0, hy1);
                *(__nv_bfloat162*)&Cl[(size_t)(m + 8) * N + n] =
                    __floats2bfloat162_rn(y0 - hy0, y1 - hy1);
            } else {
                float2 v0;
                v0.x = x0; v0.y = x1;
                float2 v1;
                v1.x = y0; v1.y = y1;
                *(float2*)&C[(size_t)m * N + n]       = v0;
                *(float2*)&C[(size_t)(m + 8) * N + n] = v1;
            }
        }
    }
}

// ---------------------------------------------------------------------------
// Tensor-core flash attention with dependency-aware MMA scheduling.
// ---------------------------------------------------------------------------
#define AP         72
#define AT_BYTES   (128 * AP * 2)
#define ASTG_BYTES (4 * AT_BYTES)
#define ASMEM      (2 * ASTG_BYTES)

__device__ __forceinline__ void attn_issue_tile(unsigned int SBM, int stage,
                                                int tile, int b, int h, int t)
{
    const int rowstr = 3 * D_MODEL;
#pragma unroll
    for (int i = 0; i < 4; i++) {
        int slot = i * 256 + t;
        int r  = slot >> 3;
        int cc = (slot & 7) * 8;
        unsigned int d = SBM + (unsigned int)(stage * ASTG_BYTES)
                       + (unsigned int)((r * AP + cc) * 2);
        size_t base = (size_t)(b * T_SEQ + tile * 128 + r) * rowstr + h * 64 + cc;
        cp16(d,                g_qh + base + D_MODEL);
        cp16(d + AT_BYTES,     g_ql + base + D_MODEL);
        cp16(d + 2 * AT_BYTES, g_qh + base + 2 * D_MODEL);
        cp16(d + 3 * AT_BYTES, g_ql + base + 2 * D_MODEL);
    }
    asm volatile("cp.async.commit_group;");
}

__global__ __launch_bounds__(256, 1) void attn_tc_kernel()
{
    extern __shared__ bf16 smb[];
    const unsigned int SBM = (unsigned int)__cvta_generic_to_shared(smb);

    const int t    = threadIdx.x;
    const int lane = t & 31;
    const int w    = t >> 5;
    const int b    = blockIdx.z;
    const int h    = blockIdx.y;
    const int q0   = blockIdx.x * 128;
    const int rowstr = 3 * D_MODEL;
    const int gr   = lane >> 2;
    const int gc   = lane & 3;

#pragma unroll
    for (int i = 0; i < 4; i++) {
        int slot = i * 256 + t;
        int r  = slot >> 3;
        int cc = (slot & 7) * 8;
        unsigned int d = SBM + (unsigned int)((r * AP + cc) * 2);
        size_t base = (size_t)(b * T_SEQ + q0 + r) * rowstr + h * 64 + cc;
        cp16(d,            g_qh + base);
        cp16(d + AT_BYTES, g_ql + base);
    }
    asm volatile("cp.async.commit_group;");
    asm volatile("cp.async.wait_group 0;");
    __syncthreads();

    unsigned int qfh[4][4];
    unsigned int qfl[4][4];
    {
        const unsigned int qoff =
            (unsigned int)((w * 16 + (lane & 15)) * AP + (lane >> 4) * 8) * 2u;
#pragma unroll
        for (int kc = 0; kc < 4; kc++) {
            ldsm4(qfh[kc], SBM + qoff + (unsigned int)(kc * 32));
            ldsm4(qfl[kc], SBM + AT_BYTES + qoff + (unsigned int)(kc * 32));
        }
    }
    __syncthreads();

    attn_issue_tile(SBM, 0, 0, b, h, t);
    attn_issue_tile(SBM, 1, 1, b, h, t);

    float sc[16][4];
    float o[8][4];
#pragma unroll
    for (int nf = 0; nf < 8; nf++)
#pragma unroll
        for (int r = 0; r < 4; r++) o[nf][r] = 0.f;
    float rm0 = -1e30f, rm1 = -1e30f, rl0 = 0.f, rl1 = 0.f;

    const unsigned int kfoff =
        (unsigned int)((lane & 15) * AP + (lane >> 4) * 8) * 2u;

    for (int it = 0; it < 16; it++) {
        if (it < 15) asm volatile("cp.async.wait_group 1;");
        else         asm volatile("cp.async.wait_group 0;");
        __syncthreads();

        const unsigned int sb = SBM + (unsigned int)((it & 1) * ASTG_BYTES);

        // ---- QK^T, ng in groups of 4, term-major (8-apart acc reuse) ----
#pragma unroll
        for (int nf = 0; nf < 16; nf++)
#pragma unroll
            for (int r = 0; r < 4; r++) sc[nf][r] = 0.f;

#pragma unroll
        for (int g = 0; g < 2; g++) {
#pragma unroll
            for (int kc = 0; kc < 4; kc++) {
                unsigned int kbh[4][4];
                unsigned int kbl[4][4];
#pragma unroll
                for (int j = 0; j < 4; j++) {
                    const unsigned int roff =
                        (unsigned int)((g * 4 + j) * 16 * AP * 2) +
                        (unsigned int)(kc * 32);
                    ldsm4(kbh[j], sb + kfoff + roff);
                    ldsm4(kbl[j], sb + AT_BYTES + kfoff + roff);
                }
#pragma unroll
                for (int j = 0; j < 4; j++) {
                    int a0 = 2 * (g * 4 + j);
                    mma16816(sc[a0],     qfh[kc], kbh[j][0], kbh[j][2]);
                    mma16816(sc[a0 + 1], qfh[kc], kbh[j][1], kbh[j][3]);
                }
#pragma unroll
                for (int j = 0; j < 4; j++) {
                    int a0 = 2 * (g * 4 + j);
                    mma16816(sc[a0],     qfh[kc], kbl[j][0], kbl[j][2]);
                    mma16816(sc[a0 + 1], qfh[kc], kbl[j][1], kbl[j][3]);
                }
#pragma unroll
                for (int j = 0; j < 4; j++) {
                    int a0 = 2 * (g * 4 + j);
                    mma16816(sc[a0],     qfl[kc], kbh[j][0], kbh[j][2]);
                    mma16816(sc[a0 + 1], qfl[kc], kbh[j][1], kbh[j][3]);
                }
            }
        }

        // ---- scale + online softmax ----
#pragma unroll
        for (int nf = 0; nf < 16; nf++) {
            sc[nf][0] *= 0.125f;
            sc[nf][1] *= 0.125f;
            sc[nf][2] *= 0.125f;
            sc[nf][3] *= 0.125f;
        }
        float mx0 = -1e30f, mx1 = -1e30f;
#pragma unroll
        for (int nf = 0; nf < 16; nf++) {
            mx0 = fmaxf(mx0, fmaxf(sc[nf][0], sc[nf][1]));
            mx1 = fmaxf(mx1, fmaxf(sc[nf][2], sc[nf][3]));
        }
        mx0 = fmaxf(mx0, __shfl_xor_sync(0xffffffffu, mx0, 1));
        mx0 = fmaxf(mx0, __shfl_xor_sync(0xffffffffu, mx0, 2));
        mx1 = fmaxf(mx1, __shfl_xor_sync(0xffffffffu, mx1, 1));
        mx1 = fmaxf(mx1, __shfl_xor_sync(0xffffffffu, mx1, 2));
        float mn0 = fmaxf(rm0, mx0);
        float mn1 = fmaxf(rm1, mx1);
        float c0 = __expf(rm0 - mn0);
        float c1 = __expf(rm1 - mn1);
        rm0 = mn0;
        rm1 = mn1;
        float ls0 = 0.f, ls1 = 0.f;
#pragma unroll
        for (int nf = 0; nf < 16; nf++) {
            sc[nf][0] = __expf(sc[nf][0] - mn0);
            sc[nf][1] = __expf(sc[nf][1] - mn0);
            sc[nf][2] = __expf(sc[nf][2] - mn1);
            sc[nf][3] = __expf(sc[nf][3] - mn1);
            ls0 += sc[nf][0] + sc[nf][1];
            ls1 += sc[nf][2] + sc[nf][3];
        }
        ls0 += __shfl_xor_sync(0xffffffffu, ls0, 1);
        ls0 += __shfl_xor_sync(0xffffffffu, ls0, 2);
        ls1 += __shfl_xor_sync(0xffffffffu, ls1, 1);
        ls1 += __shfl_xor_sync(0xffffffffu, ls1, 2);
        rl0 = rl0 * c0 + ls0;
        rl1 = rl1 * c1 + ls1;
#pragma unroll
        for (int nf = 0; nf < 8; nf++) {
            o[nf][0] *= c0;
            o[nf][1] *= c0;
            o[nf][2] *= c1;
            o[nf][3] *= c1;
        }

        // ---- PV, all dg frags hoisted, term-major (8-apart acc reuse) ----
#pragma unroll
        for (int kc = 0; kc < 8; kc++) {
            float v00 = sc[2 * kc][0],     v01 = sc[2 * kc][1];
            float v10 = sc[2 * kc][2],     v11 = sc[2 * kc][3];
            float v20 = sc[2 * kc + 1][0], v21 = sc[2 * kc + 1][1];
            float v30 = sc[2 * kc + 1][2], v31 = sc[2 * kc + 1][3];
            float h00 = __bfloat162float(__float2bfloat16(v00));
            float h01 = __bfloat162float(__float2bfloat16(v01));
            float h10 = __bfloat162float(__float2bfloat16(v10));
            float h11 = __bfloat162float(__float2bfloat16(v11));
            float h20 = __bfloat162float(__float2bfloat16(v20));
            float h21 = __bfloat162float(__float2bfloat16(v21));
            float h30 = __bfloat162float(__float2bfloat16(v30));
            float h31 = __bfloat162float(__float2bfloat16(v31));
            unsigned int pa_h[4];
            unsigned int pa_l[4];
            pa_h[0] = bpack(h00, h01);
            pa_h[1] = bpack(h10, h11);
            pa_h[2] = bpack(h20, h21);
            pa_h[3] = bpack(h30, h31);
            pa_l[0] = bpack(v00 - h00, v01 - h01);
            pa_l[1] = bpack(v10 - h10, v11 - h11);
            pa_l[2] = bpack(v20 - h20, v21 - h21);
            pa_l[3] = bpack(v30 - h30, v31 - h31);

            const unsigned int soff = (unsigned int)(kc * 16 * AP * 2);
            unsigned int vbh[4][4];
            unsigned int vbl[4][4];
#pragma unroll
            for (int dg = 0; dg < 4; dg++) {
                ldsm4t(vbh[dg], sb + 2 * AT_BYTES + kfoff + soff + (unsigned int)(dg * 32));
                ldsm4t(vbl[dg], sb + 3 * AT_BYTES + kfoff + soff + (unsigned int)(dg * 32));
            }
#pragma unroll
            for (int dg = 0; dg < 4; dg++) {
                mma16816(o[2 * dg],     pa_h, vbh[dg][0], vbh[dg][1]);
                mma16816(o[2 * dg + 1], pa_h, vbh[dg][2], vbh[dg][3]);
            }
#pragma unroll
            for (int dg = 0; dg < 4; dg++) {
                mma16816(o[2 * dg],     pa_h, vbl[dg][0], vbl[dg][1]);
                mma16816(o[2 * dg + 1], pa_h, vbl[dg][2], vbl[dg][3]);
            }
#pragma unroll
            for (int dg = 0; dg < 4; dg++) {
                mma16816(o[2 * dg],     pa_l, vbh[dg][0], vbh[dg][1]);
                mma16816(o[2 * dg + 1], pa_l, vbh[dg][2], vbh[dg][3]);
            }
        }
        __syncthreads();

        if (it + 2 < 16)
            attn_issue_tile(SBM, it & 1, it + 2, b, h, t);
    }

    // ---- epilogue ----
    float inv0 = 1.f / rl0;
    float inv1 = 1.f / rl1;
    const int row0 = q0 + w * 16 + gr;
    const int row1 = row0 + 8;
#pragma unroll
    for (int nf = 0; nf < 8; nf++) {
        int d = nf * 8 + 2 * gc;
        float a0 = o[nf][0] * inv0;
        float a1 = o[nf][1] * inv0;
        float b0v = o[nf][2] * inv1;
        float b1v = o[nf][3] * inv1;
        size_t off0 = (size_t)(b * T_SEQ + row0) * D_MODEL + h * 64 + d;
        size_t off1 = (size_t)(b * T_SEQ + row1) * D_MODEL + h * 64 + d;
        float ha0 = __bfloat162float(__float2bfloat16(a0));
        float ha1 = __bfloat162float(__float2bfloat16(a1));
        float hb0 = __bfloat162float(__float2bfloat16(b0v));
        float hb1 = __bfloat162float(__float2bfloat16(b1v));
        *(__nv_bfloat162*)&g_ah[off0] = __floats2bfloat162_rn(ha0, ha1);
        *(__nv_bfloat162*)&g_al[off0] = __floats2bfloat162_rn(a0 - ha0, a1 - ha1);
        *(__nv_bfloat162*)&g_ah[off1] = __floats2bfloat162_rn(hb0, hb1);
        *(__nv_bfloat162*)&g_al[off1] = __floats2bfloat162_rn(b0v - hb0, b1v - hb1);
    }
}

// ---------------------------------------------------------------------------
extern "C" void kernel_launch(void* const* d_in, const int* in_sizes, int n_in,
                              void* d_out, int out_size)
{
    const float* x      = (const float*)d_in[0];
    const float* qkv_w  = (const float*)d_in[1];
    const float* qkv_b  = (const float*)d_in[2];
    const float* out_w  = (const float*)d_in[3];
    const float* out_b  = (const float*)d_in[4];
    float* out = (float*)d_out;

    bf16* xh;  bf16* xl;
    bf16* wqh; bf16* wql;
    bf16* woh; bf16* wol;
    bf16* qh;  bf16* ql;
    bf16* ah;  bf16* al;
    cudaGetSymbolAddress((void**)&xh,  g_xh);
    cudaGetSymbolAddress((void**)&xl,  g_xl);
    cudaGetSymbolAddress((void**)&wqh, g_wqh);
    cudaGetSymbolAddress((void**)&wql, g_wql);
    cudaGetSymbolAddress((void**)&woh, g_woh);
    cudaGetSymbolAddress((void**)&wol, g_wol);
    cudaGetSymbolAddress((void**)&qh,  g_qh);
    cudaGetSymbolAddress((void**)&ql,  g_ql);
    cudaGetSymbolAddress((void**)&ah,  g_ah);
    cudaGetSymbolAddress((void**)&al,  g_al);

    cudaFuncSetAttribute(gemm_fused<1>,
                         cudaFuncAttributeMaxDynamicSharedMemorySize, GSMEM);
    cudaFuncSetAttribute(gemm_fused<0>,
                         cudaFuncAttributeMaxDynamicSharedMemorySize, GSMEM);
    cudaFuncSetAttribute(attn_tc_kernel,
                         cudaFuncAttributeMaxDynamicSharedMemorySize, ASMEM);

    int n4 = MTOT * D_MODEL / 4;
    split_kernel<<<(n4 + 255) / 256, 256>>>(x, xh, xl, n4);
    n4 = 3 * D_MODEL * D_MODEL / 4;
    split_kernel<<<(n4 + 255) / 256, 256>>>(qkv_w, wqh, wql, n4);
    n4 = D_MODEL * D_MODEL / 4;
    split_kernel<<<(n4 + 255) / 256, 256>>>(out_w, woh, wol, n4);

    {
        dim3 grid(3 * D_MODEL / 128, MTOT / 128);
        gemm_fused<1><<<grid, 256, GSMEM>>>(xh, xl, wqh, wql, qkv_b,
                                            (float*)0, qh, ql, 3 * D_MODEL);
    }
    {
        dim3 grid(T_SEQ / 128, N_HEAD, BATCH);
        attn_tc_kernel<<<grid, 256, ASMEM>>>();
    }
    {
        dim3 grid(D_MODEL / 128, MTOT / 128);
        gemm_fused<0><<<grid, 256, GSMEM>>>(ah, al, woh, wol, out_b,
                                            out, (bf16*)0, (bf16*)0, D_MODEL);
    }
}